// round 12
// baseline (speedup 1.0000x reference)
#include <cuda_runtime.h>
#include <cuda_bf16.h>
#include <math.h>
#include <stdint.h>

#define N_NODES 50000
#define N_EDGES 400000
#define IN_F    512
#define HID     512
#define OUT_F   256
#define N_SEL   8192
#define N_C     1024
#define N_DIM   128
#define GK      512        // K of the three big GEMMs

// ---------------- scratch (device globals) ----------------------------------
__device__ float          g_Z  [(size_t)N_NODES * HID];     // GEMM output (pre-agg)
__device__ float          g_h3 [(size_t)N_NODES * OUT_F];   // layer-3 activations
__device__ __nv_bfloat16  g_Ahi[(size_t)N_NODES * HID];
__device__ __nv_bfloat16  g_Alo[(size_t)N_NODES * HID];
__device__ __nv_bfloat16  g_W1hi[HID * GK],   g_W1lo[HID * GK];
__device__ __nv_bfloat16  g_W2hi[HID * GK],   g_W2lo[HID * GK];
__device__ __nv_bfloat16  g_W3hi[OUT_F * GK], g_W3lo[OUT_F * GK];
__device__ float          g_proj[(size_t)N_SEL * N_DIM];
__device__ float g_ns[N_NODES], g_nd[N_NODES];
__device__ int   g_deg_out[N_NODES], g_deg_in[N_NODES];
__device__ int   g_rowptr[N_NODES + 1], g_cursor[N_NODES], g_esrc[N_EDGES];
__device__ int   g_blockSums[256];

#define SCAN_BLOCKS 196   // 196*256 = 50176 >= N_NODES

// ---------------- low-level helpers ------------------------------------------
__device__ __forceinline__ uint32_t smem_u32(const void* p) {
    uint32_t a;
    asm("{ .reg .u64 t; cvta.to.shared.u64 t, %1; cvt.u32.u64 %0, t; }" : "=r"(a) : "l"(p));
    return a;
}
__device__ __forceinline__ void ldm_x4(uint32_t* r, uint32_t addr) {
    asm volatile("ldmatrix.sync.aligned.m8n8.x4.shared.b16 {%0,%1,%2,%3}, [%4];"
        : "=r"(r[0]), "=r"(r[1]), "=r"(r[2]), "=r"(r[3]) : "r"(addr));
}
__device__ __forceinline__ void mma16816(float* c, const uint32_t* a, const uint32_t* b) {
    asm volatile("mma.sync.aligned.m16n8k16.row.col.f32.bf16.bf16.f32 "
        "{%0,%1,%2,%3}, {%4,%5,%6,%7}, {%8,%9}, {%0,%1,%2,%3};"
        : "+f"(c[0]), "+f"(c[1]), "+f"(c[2]), "+f"(c[3])
        : "r"(a[0]), "r"(a[1]), "r"(a[2]), "r"(a[3]), "r"(b[0]), "r"(b[1]));
}
__device__ __forceinline__ void cp16(uint32_t saddr, const void* g) {
    asm volatile("cp.async.cg.shared.global [%0], [%1], 16;" :: "r"(saddr), "l"(g));
}
#define CP_COMMIT() asm volatile("cp.async.commit_group;" ::: "memory")
#define CP_WAIT(n)  asm volatile("cp.async.wait_group %0;" :: "n"(n) : "memory")

// ---------------- graph preprocessing ----------------------------------------
__global__ void zero_deg_kernel() {
    int i = blockIdx.x * blockDim.x + threadIdx.x;
    for (; i < N_NODES; i += gridDim.x * blockDim.x) { g_deg_out[i] = 0; g_deg_in[i] = 0; }
}
__global__ void hist_kernel(const int* __restrict__ src, const int* __restrict__ dst) {
    int i = blockIdx.x * blockDim.x + threadIdx.x;
    for (; i < N_EDGES; i += gridDim.x * blockDim.x) {
        atomicAdd(&g_deg_out[src[i]], 1);
        atomicAdd(&g_deg_in[dst[i]], 1);
    }
}
__global__ void norm_kernel() {
    int i = blockIdx.x * blockDim.x + threadIdx.x;
    for (; i < N_NODES; i += gridDim.x * blockDim.x) {
        int dout = g_deg_out[i], din = g_deg_in[i];
        g_ns[i] = dout > 0 ? rsqrtf((float)dout) : 0.0f;
        g_nd[i] = din  > 0 ? rsqrtf((float)din)  : 0.0f;
    }
}
__global__ void scan1_kernel() {
    __shared__ int sh[256];
    int b = blockIdx.x, t = threadIdx.x;
    int i = b * 256 + t;
    sh[t] = (i < N_NODES) ? g_deg_in[i] : 0;
    __syncthreads();
    #pragma unroll
    for (int off = 128; off > 0; off >>= 1) {
        if (t < off) sh[t] += sh[t + off];
        __syncthreads();
    }
    if (t == 0) g_blockSums[b] = sh[0];
}
__global__ void scan2_kernel() {
    __shared__ int sh[256];
    int t = threadIdx.x;
    int v = (t < SCAN_BLOCKS) ? g_blockSums[t] : 0;
    sh[t] = v;
    __syncthreads();
    #pragma unroll
    for (int off = 1; off < 256; off <<= 1) {
        int x = (t >= off) ? sh[t - off] : 0;
        __syncthreads();
        sh[t] += x;
        __syncthreads();
    }
    if (t < SCAN_BLOCKS) g_blockSums[t] = sh[t] - v;
    if (t == 255) g_rowptr[N_NODES] = sh[255];
}
__global__ void scan3_kernel() {
    __shared__ int sh[256];
    int b = blockIdx.x, t = threadIdx.x;
    int i = b * 256 + t;
    int v = (i < N_NODES) ? g_deg_in[i] : 0;
    sh[t] = v;
    __syncthreads();
    #pragma unroll
    for (int off = 1; off < 256; off <<= 1) {
        int x = (t >= off) ? sh[t - off] : 0;
        __syncthreads();
        sh[t] += x;
        __syncthreads();
    }
    if (i < N_NODES) {
        int excl = g_blockSums[b] + sh[t] - v;
        g_rowptr[i] = excl;
        g_cursor[i] = excl;
    }
}
__global__ void fill_kernel(const int* __restrict__ src, const int* __restrict__ dst) {
    int i = blockIdx.x * blockDim.x + threadIdx.x;
    for (; i < N_EDGES; i += gridDim.x * blockDim.x) {
        int p = atomicAdd(&g_cursor[dst[i]], 1);
        g_esrc[p] = src[i];
    }
}

// ---------------- hi/lo splitting ---------------------------------------------
__device__ __forceinline__ void split2(float a, float b, uint32_t& hi, uint32_t& lo) {
    __nv_bfloat16 ha = __float2bfloat16_rn(a);
    __nv_bfloat16 hb = __float2bfloat16_rn(b);
    __nv_bfloat16 la = __float2bfloat16_rn(a - __bfloat162float(ha));
    __nv_bfloat16 lb = __float2bfloat16_rn(b - __bfloat162float(hb));
    hi = (uint32_t)__bfloat16_as_ushort(ha) | ((uint32_t)__bfloat16_as_ushort(hb) << 16);
    lo = (uint32_t)__bfloat16_as_ushort(la) | ((uint32_t)__bfloat16_as_ushort(lb) << 16);
}

__global__ void conv_x_kernel(const float* __restrict__ x) {
    const float4* x4 = (const float4*)x;
    uint2* hi2 = (uint2*)g_Ahi;
    uint2* lo2 = (uint2*)g_Alo;
    size_t total = (size_t)N_NODES * IN_F / 4;
    for (size_t i = blockIdx.x * blockDim.x + threadIdx.x; i < total;
         i += (size_t)gridDim.x * blockDim.x) {
        float4 v = x4[i];
        uint2 h, l;
        split2(v.x, v.y, h.x, l.x);
        split2(v.z, v.w, h.y, l.y);
        hi2[i] = h;
        lo2[i] = l;
    }
}

// W [K, N] row-major -> W^T hi/lo stored [N, K]
__global__ void wprep_kernel(const float* __restrict__ W, __nv_bfloat16* __restrict__ Whi,
                             __nv_bfloat16* __restrict__ Wlo, int Kd, int Nd) {
    int total = Kd * Nd;
    for (int idx = blockIdx.x * blockDim.x + threadIdx.x; idx < total;
         idx += gridDim.x * blockDim.x) {
        int n = idx / Kd, k = idx - n * Kd;
        float v = W[(size_t)k * Nd + n];
        __nv_bfloat16 h = __float2bfloat16_rn(v);
        __nv_bfloat16 l = __float2bfloat16_rn(v - __bfloat162float(h));
        Whi[idx] = h;
        Wlo[idx] = l;
    }
}

// ---------------- tensor-core GEMM (exact R8 config) ---------------------------
#define SROW 80                        // bytes per smem row (40 bf16)
#define TILE_BYTES (128 * SROW)        // 10240 B
#define STAGE_BYTES (4 * TILE_BYTES)   // 40960 B
#define GEMM_SMEM (2 * STAGE_BYTES)    // 81920 B dynamic

// 128x32 bf16 tile loader, sequential rows (clamped)
__device__ __forceinline__ void issue_rows(const __nv_bfloat16* __restrict__ G,
                                           int row0, int rmax, int rstride,
                                           uint32_t sbase, int k0, int tid) {
    const char* g = (const char*)G;
    #pragma unroll
    for (int i = 0; i < 2; i++) {
        int v = tid + 256 * i;            // 0..511
        int r = v >> 2, c = v & 3;        // 128 rows x 4 x 16B
        int gr = row0 + r;
        gr = gr < rmax ? gr : rmax - 1;
        cp16(sbase + r * SROW + c * 16,
             g + ((size_t)gr * rstride + k0) * 2 + c * 16);
    }
}

// C[M,N] = (Ahi+Alo)[M,K] @ ((Whi+Wlo)[N,K])^T, 3-term split, fp32 acc
// 8 warps, warp tile 64x32, 2 stages, single sync per chunk (R8 config).
template <int KDIM>
__global__ __launch_bounds__(256, 2)
void gemm_mma_kernel(const __nv_bfloat16* __restrict__ Ahi, const __nv_bfloat16* __restrict__ Alo,
                     const __nv_bfloat16* __restrict__ Whi, const __nv_bfloat16* __restrict__ Wlo,
                     float* __restrict__ C, int M, int N) {
    extern __shared__ __align__(16) char sm[];
    uint32_t u0 = smem_u32(sm);

    int tid = threadIdx.x;
    int wid = tid >> 5, lane = tid & 31;
    int tile_m = blockIdx.y * 128, tile_n = blockIdx.x * 128;
    int warp_m = (wid >> 2) * 64;
    int warp_n = (wid & 3) * 32;

    float acc[4][4][4];
    #pragma unroll
    for (int a = 0; a < 4; a++)
        #pragma unroll
        for (int b = 0; b < 4; b++)
            #pragma unroll
            for (int c = 0; c < 4; c++) acc[a][b][c] = 0.0f;

    int a_r  = lane & 15;
    int a_ko = (lane >> 4) << 3;
    int b_g  = lane >> 3, b_i = lane & 7;
    int b_nr = ((b_g >> 1) << 3) + b_i;
    int b_ko = (b_g & 1) << 3;

    const int NCH = KDIM / 32;

    {   // prefetch chunk 0 into stage 0
        uint32_t st = u0;
        issue_rows(Ahi, tile_m, M, KDIM, st,                  0, tid);
        issue_rows(Alo, tile_m, M, KDIM, st + TILE_BYTES,     0, tid);
        issue_rows(Whi, tile_n, N, KDIM, st + 2 * TILE_BYTES, 0, tid);
        issue_rows(Wlo, tile_n, N, KDIM, st + 3 * TILE_BYTES, 0, tid);
        CP_COMMIT();
    }

    for (int ch = 0; ch < NCH; ch++) {
        CP_WAIT(0);
        __syncthreads();   // data for ch visible; other stage free

        if (ch + 1 < NCH) {
            uint32_t st = u0 + ((ch + 1) & 1) * STAGE_BYTES;
            int k0g = (ch + 1) * 32;
            issue_rows(Ahi, tile_m, M, KDIM, st,                  k0g, tid);
            issue_rows(Alo, tile_m, M, KDIM, st + TILE_BYTES,     k0g, tid);
            issue_rows(Whi, tile_n, N, KDIM, st + 2 * TILE_BYTES, k0g, tid);
            issue_rows(Wlo, tile_n, N, KDIM, st + 3 * TILE_BYTES, k0g, tid);
            CP_COMMIT();
        }

        uint32_t stc = u0 + (ch & 1) * STAGE_BYTES;
        uint32_t uAH = stc, uAL = stc + TILE_BYTES;
        uint32_t uWH = stc + 2 * TILE_BYTES, uWL = stc + 3 * TILE_BYTES;

        #pragma unroll
        for (int ks = 0; ks < 2; ks++) {
            int k0 = ks * 16;
            uint32_t bh[2][4], bl[2][4], af[4][4];
            #pragma unroll
            for (int t = 0; t < 2; t++) {
                uint32_t noff = (uint32_t)(warp_n + t * 16 + b_nr) * SROW + (k0 + b_ko) * 2;
                ldm_x4(bh[t], uWH + noff);
                ldm_x4(bl[t], uWL + noff);
            }
            #pragma unroll
            for (int mt = 0; mt < 4; mt++) {
                uint32_t moff = (uint32_t)(warp_m + mt * 16 + a_r) * SROW + (k0 + a_ko) * 2;
                ldm_x4(af[mt], uAH + moff);
            }
            #pragma unroll
            for (int mt = 0; mt < 4; mt++)
                #pragma unroll
                for (int nt = 0; nt < 4; nt++) {
                    mma16816(acc[mt][nt], af[mt], &bh[nt >> 1][(nt & 1) * 2]);
                    mma16816(acc[mt][nt], af[mt], &bl[nt >> 1][(nt & 1) * 2]);
                }
            #pragma unroll
            for (int mt = 0; mt < 4; mt++) {
                uint32_t moff = (uint32_t)(warp_m + mt * 16 + a_r) * SROW + (k0 + a_ko) * 2;
                ldm_x4(af[mt], uAL + moff);
            }
            #pragma unroll
            for (int mt = 0; mt < 4; mt++)
                #pragma unroll
                for (int nt = 0; nt < 4; nt++)
                    mma16816(acc[mt][nt], af[mt], &bh[nt >> 1][(nt & 1) * 2]);
        }
    }

    int er = lane >> 2, ec = (lane & 3) << 1;
    #pragma unroll
    for (int mt = 0; mt < 4; mt++) {
        #pragma unroll
        for (int nt = 0; nt < 4; nt++) {
            int r0 = tile_m + warp_m + mt * 16 + er;
            int c0 = tile_n + warp_n + nt * 8 + ec;
            if (r0 < M)
                *(float2*)&C[(size_t)r0 * N + c0] = make_float2(acc[mt][nt][0], acc[mt][nt][1]);
            if (r0 + 8 < M)
                *(float2*)&C[(size_t)(r0 + 8) * N + c0] = make_float2(acc[mt][nt][2], acc[mt][nt][3]);
        }
    }
}

// ---------------- feature-chunked CSR aggregation ------------------------------
// grid = (N_NODES/8, F/128); warp = one node x one 128-float feature chunk.
// bf16_out: layers 1-2 emit bf16 hi/lo; layer 3 emits fp32 h3.
__global__ __launch_bounds__(256)
void agg_kernel(const float* __restrict__ Z, const float* __restrict__ bias,
                float* __restrict__ outF,
                __nv_bfloat16* __restrict__ outHi, __nv_bfloat16* __restrict__ outLo,
                int F, int bf16_out) {
    int node = blockIdx.x * 8 + (threadIdx.x >> 5);
    int lane = threadIdx.x & 31;
    int chunk = blockIdx.y;
    int nvec = F >> 2;                  // float4 per row
    int col = chunk * 32 + lane;        // float4 column index

    float4 acc = make_float4(0.f, 0.f, 0.f, 0.f);
    int beg = g_rowptr[node], end = g_rowptr[node + 1];
    const float4* Z4 = (const float4*)Z;
    for (int e = beg; e < end; ++e) {
        int s = g_esrc[e];
        float w = g_ns[s];
        float4 z = Z4[(size_t)s * nvec + col];
        acc.x = fmaf(w, z.x, acc.x);
        acc.y = fmaf(w, z.y, acc.y);
        acc.z = fmaf(w, z.z, acc.z);
        acc.w = fmaf(w, z.w, acc.w);
    }
    float ndv = g_nd[node];
    float4 b = ((const float4*)bias)[col];
    float4 r;
    r.x = fmaxf(fmaf(ndv, acc.x, b.x), 0.f);
    r.y = fmaxf(fmaf(ndv, acc.y, b.y), 0.f);
    r.z = fmaxf(fmaf(ndv, acc.z, b.z), 0.f);
    r.w = fmaxf(fmaf(ndv, acc.w, b.w), 0.f);
    if (bf16_out) {
        uint2 h, l;
        split2(r.x, r.y, h.x, l.x);
        split2(r.z, r.w, h.y, l.y);
        ((uint2*)outHi)[(size_t)node * nvec + col] = h;
        ((uint2*)outLo)[(size_t)node * nvec + col] = l;
    } else {
        ((float4*)outF)[(size_t)node * nvec + col] = r;
    }
}

// ---------------- tiled proj: proj = h3[xidx] @ Wp + bp -------------------------
// grid = N_SEL/64 blocks x 128 threads. enc tile (64x256 fp32) in smem;
// Wp (131 KB) becomes L1-resident across the 64-row loop.
#define PROJ_SMEM (64 * OUT_F * 4)     // 65536 B
__global__ __launch_bounds__(128)
void proj_tiled_kernel(const float* __restrict__ H, const int* __restrict__ xidx,
                       const float* __restrict__ Wp, const float* __restrict__ bp,
                       float* __restrict__ P) {
    extern __shared__ float enc[];     // [64][256]
    int b = blockIdx.x;
    int t = threadIdx.x;               // 0..127 = output dim
    // load 64 selected rows (coalesced 512B chunks)
    for (int i = t; i < 64 * OUT_F / 4; i += 128) {
        int r = i / (OUT_F / 4), c = i % (OUT_F / 4);
        int row = xidx[b * 64 + r];
        ((float4*)enc)[r * (OUT_F / 4) + c] =
            ((const float4*)H)[(size_t)row * (OUT_F / 4) + c];
    }
    __syncthreads();
    float bpv = bp[t];
    for (int r = 0; r < 64; r++) {
        const float* e = enc + r * OUT_F;
        float a0 = 0.f, a1 = 0.f, a2 = 0.f, a3 = 0.f;
        #pragma unroll 8
        for (int k = 0; k < OUT_F; k += 4) {
            a0 = fmaf(e[k + 0], Wp[(size_t)(k + 0) * N_DIM + t], a0);
            a1 = fmaf(e[k + 1], Wp[(size_t)(k + 1) * N_DIM + t], a1);
            a2 = fmaf(e[k + 2], Wp[(size_t)(k + 2) * N_DIM + t], a2);
            a3 = fmaf(e[k + 3], Wp[(size_t)(k + 3) * N_DIM + t], a3);
        }
        P[(size_t)(b * 64 + r) * N_DIM + t] = bpv + (a0 + a1) + (a2 + a3);
    }
}

// ---------------- out[c][s] = dot(emb[c_indices[c]], proj[s])  (K=128) ---------
__global__ __launch_bounds__(256)
void out_gemm_kernel(const float* __restrict__ emb, const int* __restrict__ cidx,
                     const float* __restrict__ P, float* __restrict__ out) {
    __shared__ float Es[64][33];
    __shared__ float Ps[64][33];
    int s0 = blockIdx.x * 64;
    int c0 = blockIdx.y * 64;
    int tid = threadIdx.x;
    int tx = tid & 15, ty = tid >> 4;

    float acc[4][4];
    #pragma unroll
    for (int i = 0; i < 4; i++)
        #pragma unroll
        for (int j = 0; j < 4; j++) acc[i][j] = 0.f;

    for (int k0 = 0; k0 < N_DIM; k0 += 32) {
        #pragma unroll
        for (int i = 0; i < 2; i++) {
            int idx = tid * 2 + i;
            int r = idx >> 3;
            int c = (idx & 7) * 4;
            int erow = cidx[c0 + r];
            float4 v = *(const float4*)&emb[(size_t)erow * N_DIM + k0 + c];
            Es[r][c] = v.x; Es[r][c + 1] = v.y; Es[r][c + 2] = v.z; Es[r][c + 3] = v.w;
            float4 p = *(const float4*)&P[(size_t)(s0 + r) * N_DIM + k0 + c];
            Ps[r][c] = p.x; Ps[r][c + 1] = p.y; Ps[r][c + 2] = p.z; Ps[r][c + 3] = p.w;
        }
        __syncthreads();
        #pragma unroll
        for (int kk = 0; kk < 32; kk++) {
            float a[4], b[4];
            #pragma unroll
            for (int i = 0; i < 4; i++) a[i] = Es[ty * 4 + i][kk];
            #pragma unroll
            for (int j = 0; j < 4; j++) b[j] = Ps[tx * 4 + j][kk];
            #pragma unroll
            for (int i = 0; i < 4; i++)
                #pragma unroll
                for (int j = 0; j < 4; j++) acc[i][j] = fmaf(a[i], b[j], acc[i][j]);
        }
        __syncthreads();
    }
    #pragma unroll
    for (int i = 0; i < 4; i++) {
        float4 v = make_float4(acc[i][0], acc[i][1], acc[i][2], acc[i][3]);
        *(float4*)&out[(size_t)(c0 + ty * 4 + i) * N_SEL + s0 + tx * 4] = v;
    }
}

// ---------------- launch --------------------------------------------------------
extern "C" void kernel_launch(void* const* d_in, const int* in_sizes, int n_in,
                              void* d_out, int out_size) {
    const float* x    = (const float*)d_in[0];
    const int*   src  = (const int*)d_in[1];
    const int*   dst  = (const int*)d_in[2];
    const int*   xidx = (const int*)d_in[3];
    const int*   cidx = (const int*)d_in[4];
    const float* W1   = (const float*)d_in[5];
    const float* b1   = (const float*)d_in[6];
    const float* W2   = (const float*)d_in[7];
    const float* b2   = (const float*)d_in[8];
    const float* W3   = (const float*)d_in[9];
    const float* b3   = (const float*)d_in[10];
    const float* Wp   = (const float*)d_in[11];
    const float* bp   = (const float*)d_in[12];
    const float* emb  = (const float*)d_in[13];
    float* out = (float*)d_out;

    static int smem_set = 0;
    if (!smem_set) {
        cudaFuncSetAttribute(gemm_mma_kernel<GK>,
                             cudaFuncAttributeMaxDynamicSharedMemorySize, GEMM_SMEM);
        cudaFuncSetAttribute(proj_tiled_kernel,
                             cudaFuncAttributeMaxDynamicSharedMemorySize, PROJ_SMEM);
        smem_set = 1;
    }

    float *Zb, *h3b, *projb;
    __nv_bfloat16 *Ahi, *Alo, *W1hi, *W1lo, *W2hi, *W2lo, *W3hi, *W3lo;
    cudaGetSymbolAddress((void**)&Zb, g_Z);
    cudaGetSymbolAddress((void**)&h3b, g_h3);
    cudaGetSymbolAddress((void**)&projb, g_proj);
    cudaGetSymbolAddress((void**)&Ahi, g_Ahi);
    cudaGetSymbolAddress((void**)&Alo, g_Alo);
    cudaGetSymbolAddress((void**)&W1hi, g_W1hi);
    cudaGetSymbolAddress((void**)&W1lo, g_W1lo);
    cudaGetSymbolAddress((void**)&W2hi, g_W2hi);
    cudaGetSymbolAddress((void**)&W2lo, g_W2lo);
    cudaGetSymbolAddress((void**)&W3hi, g_W3hi);
    cudaGetSymbolAddress((void**)&W3lo, g_W3lo);

    const int MB = (N_NODES + 127) / 128;   // 391

    // GEMM L1 at launch index 3 (ncu capture slot)
    conv_x_kernel<<<512, 256>>>(x);                                     // 0
    wprep_kernel<<<256, 256>>>(W1, W1hi, W1lo, GK, HID);                // 1
    wprep_kernel<<<256, 256>>>(W2, W2hi, W2lo, GK, HID);                // 2
    gemm_mma_kernel<GK><<<dim3(HID / 128, MB), 256, GEMM_SMEM>>>(       // 3  <- ncu
        Ahi, Alo, W1hi, W1lo, Zb, N_NODES, HID);
    wprep_kernel<<<128, 256>>>(W3, W3hi, W3lo, GK, OUT_F);              // 4

    // graph preprocessing (needed before first agg)
    zero_deg_kernel<<<196, 256>>>();
    hist_kernel<<<512, 256>>>(src, dst);
    norm_kernel<<<196, 256>>>();
    scan1_kernel<<<SCAN_BLOCKS, 256>>>();
    scan2_kernel<<<1, 256>>>();
    scan3_kernel<<<SCAN_BLOCKS, 256>>>();
    fill_kernel<<<512, 256>>>(src, dst);

    // Layer 1 aggregation (feature-chunked, bf16 out)
    agg_kernel<<<dim3(N_NODES / 8, HID / 128), 256>>>(Zb, b1, nullptr, Ahi, Alo, HID, 1);

    // Layer 2
    gemm_mma_kernel<GK><<<dim3(HID / 128, MB), 256, GEMM_SMEM>>>(
        Ahi, Alo, W2hi, W2lo, Zb, N_NODES, HID);
    agg_kernel<<<dim3(N_NODES / 8, HID / 128), 256>>>(Zb, b2, nullptr, Ahi, Alo, HID, 1);

    // Layer 3 (N = 256): agg emits fp32 h3
    gemm_mma_kernel<GK><<<dim3(OUT_F / 128, MB), 256, GEMM_SMEM>>>(
        Ahi, Alo, W3hi, W3lo, Zb, N_NODES, OUT_F);
    agg_kernel<<<dim3(N_NODES / 8, OUT_F / 128), 256>>>(Zb, b3, h3b, nullptr, nullptr, OUT_F, 0);

    // proj = h3[x_indices] @ Wp + bp  (tiled, Wp L1-resident per block)
    proj_tiled_kernel<<<N_SEL / 64, 128, PROJ_SMEM>>>(h3b, xidx, Wp, bp, projb);

    // out = emb[c_indices] @ proj.T
    out_gemm_kernel<<<dim3(N_SEL / 64, N_C / 64), 256>>>(emb, cidx, projb, out);
}

// round 13
// speedup vs baseline: 1.5252x; 1.5252x over previous
#include <cuda_runtime.h>
#include <cuda_fp16.h>
#include <math.h>
#include <stdint.h>

#define N_NODES 50000
#define N_EDGES 400000
#define IN_F    512
#define HID     512
#define OUT_F   256
#define N_SEL   8192
#define N_C     1024
#define N_DIM   128
#define GK      512        // K of the three big GEMMs

// ---------------- scratch (device globals) ----------------------------------
__device__ float   g_Z  [(size_t)N_NODES * HID];     // GEMM output (pre-agg)
__device__ __half  g_A  [(size_t)N_NODES * HID];     // activations, single fp16
__device__ __half  g_W1hi[HID * GK],   g_W1lo[HID * GK];
__device__ __half  g_W2hi[HID * GK],   g_W2lo[HID * GK];
__device__ __half  g_W3hi[OUT_F * GK], g_W3lo[OUT_F * GK];
__device__ __half  g_H3hi[(size_t)N_NODES * OUT_F], g_H3lo[(size_t)N_NODES * OUT_F];
__device__ __half  g_Gf [N_C * OUT_F];               // G single fp16
__device__ __half  g_Ehi[(size_t)N_SEL * OUT_F], g_Elo[(size_t)N_SEL * OUT_F];
__device__ float   g_t[N_C];
__device__ float g_ns[N_NODES], g_nd[N_NODES];
__device__ int   g_deg_out[N_NODES], g_deg_in[N_NODES];
__device__ int   g_rowptr[N_NODES + 1], g_cursor[N_NODES], g_esrc[N_EDGES];
__device__ int   g_blockSums[256];

#define SCAN_BLOCKS 196   // 196*256 = 50176 >= N_NODES

// ---------------- low-level helpers ------------------------------------------
__device__ __forceinline__ uint32_t smem_u32(const void* p) {
    uint32_t a;
    asm("{ .reg .u64 t; cvta.to.shared.u64 t, %1; cvt.u32.u64 %0, t; }" : "=r"(a) : "l"(p));
    return a;
}
__device__ __forceinline__ void ldm_x4(uint32_t* r, uint32_t addr) {
    asm volatile("ldmatrix.sync.aligned.m8n8.x4.shared.b16 {%0,%1,%2,%3}, [%4];"
        : "=r"(r[0]), "=r"(r[1]), "=r"(r[2]), "=r"(r[3]) : "r"(addr));
}
__device__ __forceinline__ void mma16816(float* c, const uint32_t* a, const uint32_t* b) {
    asm volatile("mma.sync.aligned.m16n8k16.row.col.f32.f16.f16.f32 "
        "{%0,%1,%2,%3}, {%4,%5,%6,%7}, {%8,%9}, {%0,%1,%2,%3};"
        : "+f"(c[0]), "+f"(c[1]), "+f"(c[2]), "+f"(c[3])
        : "r"(a[0]), "r"(a[1]), "r"(a[2]), "r"(a[3]), "r"(b[0]), "r"(b[1]));
}
__device__ __forceinline__ void cp16(uint32_t saddr, const void* g) {
    asm volatile("cp.async.cg.shared.global [%0], [%1], 16;" :: "r"(saddr), "l"(g));
}
#define CP_COMMIT() asm volatile("cp.async.commit_group;" ::: "memory")
#define CP_WAIT(n)  asm volatile("cp.async.wait_group %0;" :: "n"(n) : "memory")

__device__ __forceinline__ uint32_t pack_h2(float a, float b) {
    __half2 h = __floats2half2_rn(a, b);
    return *(uint32_t*)&h;
}

// ---------------- graph preprocessing ----------------------------------------
__global__ void zero_deg_kernel() {
    int i = blockIdx.x * blockDim.x + threadIdx.x;
    for (; i < N_NODES; i += gridDim.x * blockDim.x) { g_deg_out[i] = 0; g_deg_in[i] = 0; }
}
__global__ void hist_kernel(const int* __restrict__ src, const int* __restrict__ dst) {
    int i = blockIdx.x * blockDim.x + threadIdx.x;
    for (; i < N_EDGES; i += gridDim.x * blockDim.x) {
        atomicAdd(&g_deg_out[src[i]], 1);
        atomicAdd(&g_deg_in[dst[i]], 1);
    }
}
__global__ void norm_kernel() {
    int i = blockIdx.x * blockDim.x + threadIdx.x;
    for (; i < N_NODES; i += gridDim.x * blockDim.x) {
        int dout = g_deg_out[i], din = g_deg_in[i];
        g_ns[i] = dout > 0 ? rsqrtf((float)dout) : 0.0f;
        g_nd[i] = din  > 0 ? rsqrtf((float)din)  : 0.0f;
    }
}
__global__ void scan1_kernel() {
    __shared__ int sh[256];
    int b = blockIdx.x, t = threadIdx.x;
    int i = b * 256 + t;
    sh[t] = (i < N_NODES) ? g_deg_in[i] : 0;
    __syncthreads();
    #pragma unroll
    for (int off = 128; off > 0; off >>= 1) {
        if (t < off) sh[t] += sh[t + off];
        __syncthreads();
    }
    if (t == 0) g_blockSums[b] = sh[0];
}
__global__ void scan2_kernel() {
    __shared__ int sh[256];
    int t = threadIdx.x;
    int v = (t < SCAN_BLOCKS) ? g_blockSums[t] : 0;
    sh[t] = v;
    __syncthreads();
    #pragma unroll
    for (int off = 1; off < 256; off <<= 1) {
        int x = (t >= off) ? sh[t - off] : 0;
        __syncthreads();
        sh[t] += x;
        __syncthreads();
    }
    if (t < SCAN_BLOCKS) g_blockSums[t] = sh[t] - v;
    if (t == 255) g_rowptr[N_NODES] = sh[255];
}
__global__ void scan3_kernel() {
    __shared__ int sh[256];
    int b = blockIdx.x, t = threadIdx.x;
    int i = b * 256 + t;
    int v = (i < N_NODES) ? g_deg_in[i] : 0;
    sh[t] = v;
    __syncthreads();
    #pragma unroll
    for (int off = 1; off < 256; off <<= 1) {
        int x = (t >= off) ? sh[t - off] : 0;
        __syncthreads();
        sh[t] += x;
        __syncthreads();
    }
    if (i < N_NODES) {
        int excl = g_blockSums[b] + sh[t] - v;
        g_rowptr[i] = excl;
        g_cursor[i] = excl;
    }
}
__global__ void fill_kernel(const int* __restrict__ src, const int* __restrict__ dst) {
    int i = blockIdx.x * blockDim.x + threadIdx.x;
    for (; i < N_EDGES; i += gridDim.x * blockDim.x) {
        int p = atomicAdd(&g_cursor[dst[i]], 1);
        g_esrc[p] = src[i];
    }
}

// ---------------- data prep ----------------------------------------------------
// x (fp32) -> single fp16 activations
__global__ void conv_x_kernel(const float* __restrict__ x) {
    const float4* x4 = (const float4*)x;
    uint2* a2 = (uint2*)g_A;
    size_t total = (size_t)N_NODES * IN_F / 4;
    for (size_t i = blockIdx.x * blockDim.x + threadIdx.x; i < total;
         i += (size_t)gridDim.x * blockDim.x) {
        float4 v = x4[i];
        uint2 u;
        u.x = pack_h2(v.x, v.y);
        u.y = pack_h2(v.z, v.w);
        a2[i] = u;
    }
}

// W [K, N] row-major -> W^T fp16 hi/lo stored [N, K]
__global__ void wprep_kernel(const float* __restrict__ W, __half* __restrict__ Whi,
                             __half* __restrict__ Wlo, int Kd, int Nd) {
    int total = Kd * Nd;
    for (int idx = blockIdx.x * blockDim.x + threadIdx.x; idx < total;
         idx += gridDim.x * blockDim.x) {
        int n = idx / Kd, k = idx - n * Kd;
        float v = W[(size_t)k * Nd + n];
        __half h = __float2half_rn(v);
        Whi[idx] = h;
        Wlo[idx] = __float2half_rn(v - __half2float(h));
    }
}

// G[c,f] = emb[cidx[c]] . Wp[f,:]; t[c] = emb_c . bp   (G single fp16)
__global__ __launch_bounds__(256)
void gmat_kernel(const float* __restrict__ emb, const int* __restrict__ cidx,
                 const float* __restrict__ Wp, const float* __restrict__ bp) {
    __shared__ float e[N_DIM];
    __shared__ float tp[N_DIM];
    int c = blockIdx.x;
    int t = threadIdx.x;
    int row = cidx[c];
    if (t < N_DIM) {
        float ev = emb[(size_t)row * N_DIM + t];
        e[t] = ev;
        tp[t] = ev * bp[t];
    }
    __syncthreads();
    const float* w = Wp + (size_t)t * N_DIM;
    float a0 = 0.f, a1 = 0.f, a2 = 0.f, a3 = 0.f;
    #pragma unroll 8
    for (int d = 0; d < N_DIM; d += 4) {
        a0 = fmaf(e[d + 0], w[d + 0], a0);
        a1 = fmaf(e[d + 1], w[d + 1], a1);
        a2 = fmaf(e[d + 2], w[d + 2], a2);
        a3 = fmaf(e[d + 3], w[d + 3], a3);
    }
    float acc = (a0 + a1) + (a2 + a3);
    g_Gf[c * OUT_F + t] = __float2half_rn(acc);
    if (t == 0) {
        float s = 0.f;
        #pragma unroll
        for (int d = 0; d < N_DIM; d++) s += tp[d];
        g_t[c] = s;
    }
}

// dense pre-gather: E(hi/lo) = h3(hi/lo)[xidx]
__global__ __launch_bounds__(256)
void enc_gather_kernel(const int* __restrict__ xidx) {
    int i = blockIdx.x * blockDim.x + threadIdx.x;   // over N_SEL*32
    int s = i >> 5, c = i & 31;                       // 32 uint4 per 256-fp16 row
    int r = xidx[s];
    ((uint4*)g_Ehi)[(size_t)s * 32 + c] = ((const uint4*)g_H3hi)[(size_t)r * 32 + c];
    ((uint4*)g_Elo)[(size_t)s * 32 + c] = ((const uint4*)g_H3lo)[(size_t)r * 32 + c];
}

// ---------------- tensor-core GEMM: 2-term fp16 (A single, W hi/lo) ------------
#define SROW 80                        // bytes per smem row (32 fp16 data + pad)
#define TILE_BYTES (128 * SROW)        // 10240 B
#define STAGE_BYTES (3 * TILE_BYTES)   // 30720 B (A, Whi, Wlo)
#define GEMM_SMEM (2 * STAGE_BYTES)    // 61440 B dynamic

// 128x32 fp16 tile loader, sequential rows (clamped)
__device__ __forceinline__ void issue_rows(const __half* __restrict__ G,
                                           int row0, int rmax, int rstride,
                                           uint32_t sbase, int k0, int tid) {
    const char* g = (const char*)G;
    #pragma unroll
    for (int i = 0; i < 2; i++) {
        int v = tid + 256 * i;            // 0..511
        int r = v >> 2, c = v & 3;        // 128 rows x 4 x 16B
        int gr = row0 + r;
        gr = gr < rmax ? gr : rmax - 1;
        cp16(sbase + r * SROW + c * 16,
             g + ((size_t)gr * rstride + k0) * 2 + c * 16);
    }
}

// C[M,N] (+opt row-bias g_t) = A[M,K] @ ((Whi+Wlo)[N,K])^T, fp32 acc
// 8 warps, warp tile 64x32, 2 stages, single sync per chunk (R8 structure).
template <int KDIM, bool ADD_T>
__global__ __launch_bounds__(256, 2)
void gemm_mma_kernel(const __half* __restrict__ A,
                     const __half* __restrict__ Whi, const __half* __restrict__ Wlo,
                     float* __restrict__ C, int M, int N) {
    extern __shared__ __align__(16) char sm[];
    uint32_t u0 = smem_u32(sm);

    int tid = threadIdx.x;
    int wid = tid >> 5, lane = tid & 31;
    int tile_m = blockIdx.y * 128, tile_n = blockIdx.x * 128;
    int warp_m = (wid >> 2) * 64;
    int warp_n = (wid & 3) * 32;

    float acc[4][4][4];
    #pragma unroll
    for (int a = 0; a < 4; a++)
        #pragma unroll
        for (int b = 0; b < 4; b++)
            #pragma unroll
            for (int c = 0; c < 4; c++) acc[a][b][c] = 0.0f;

    int a_r  = lane & 15;
    int a_ko = (lane >> 4) << 3;
    int b_g  = lane >> 3, b_i = lane & 7;
    int b_nr = ((b_g >> 1) << 3) + b_i;
    int b_ko = (b_g & 1) << 3;

    const int NCH = KDIM / 32;

    {   // prefetch chunk 0 into stage 0
        uint32_t st = u0;
        issue_rows(A,   tile_m, M, KDIM, st,                  0, tid);
        issue_rows(Whi, tile_n, N, KDIM, st + TILE_BYTES,     0, tid);
        issue_rows(Wlo, tile_n, N, KDIM, st + 2 * TILE_BYTES, 0, tid);
        CP_COMMIT();
    }

    for (int ch = 0; ch < NCH; ch++) {
        CP_WAIT(0);
        __syncthreads();   // data for ch visible; other stage free

        if (ch + 1 < NCH) {
            uint32_t st = u0 + ((ch + 1) & 1) * STAGE_BYTES;
            int k0g = (ch + 1) * 32;
            issue_rows(A,   tile_m, M, KDIM, st,                  k0g, tid);
            issue_rows(Whi, tile_n, N, KDIM, st + TILE_BYTES,     k0g, tid);
            issue_rows(Wlo, tile_n, N, KDIM, st + 2 * TILE_BYTES, k0g, tid);
            CP_COMMIT();
        }

        uint32_t stc = u0 + (ch & 1) * STAGE_BYTES;
        uint32_t uA = stc;
        uint32_t uWH = stc + TILE_BYTES, uWL = stc + 2 * TILE_BYTES;

        #pragma unroll
        for (int ks = 0; ks < 2; ks++) {
            int k0 = ks * 16;
            uint32_t bh[2][4], bl[2][4], af[4][4];
            #pragma unroll
            for (int t = 0; t < 2; t++) {
                uint32_t noff = (uint32_t)(warp_n + t * 16 + b_nr) * SROW + (k0 + b_ko) * 2;
                ldm_x4(bh[t], uWH + noff);
                ldm_x4(bl[t], uWL + noff);
            }
            #pragma unroll
            for (int mt = 0; mt < 4; mt++) {
                uint32_t moff = (uint32_t)(warp_m + mt * 16 + a_r) * SROW + (k0 + a_ko) * 2;
                ldm_x4(af[mt], uA + moff);
            }
            #pragma unroll
            for (int mt = 0; mt < 4; mt++)
                #pragma unroll
                for (int nt = 0; nt < 4; nt++) {
                    mma16816(acc[mt][nt], af[mt], &bh[nt >> 1][(nt & 1) * 2]);
                    mma16816(acc[mt][nt], af[mt], &bl[nt >> 1][(nt & 1) * 2]);
                }
        }
    }

    int er = lane >> 2, ec = (lane & 3) << 1;
    #pragma unroll
    for (int mt = 0; mt < 4; mt++) {
        #pragma unroll
        for (int nt = 0; nt < 4; nt++) {
            int r0 = tile_m + warp_m + mt * 16 + er;
            int c0 = tile_n + warp_n + nt * 8 + ec;
            if (ADD_T) {
                float t0 = g_t[r0], t1 = g_t[r0 + 8];
                *(float2*)&C[(size_t)r0 * N + c0] =
                    make_float2(acc[mt][nt][0] + t0, acc[mt][nt][1] + t0);
                *(float2*)&C[(size_t)(r0 + 8) * N + c0] =
                    make_float2(acc[mt][nt][2] + t1, acc[mt][nt][3] + t1);
            } else {
                if (r0 < M)
                    *(float2*)&C[(size_t)r0 * N + c0] = make_float2(acc[mt][nt][0], acc[mt][nt][1]);
                if (r0 + 8 < M)
                    *(float2*)&C[(size_t)(r0 + 8) * N + c0] = make_float2(acc[mt][nt][2], acc[mt][nt][3]);
            }
        }
    }
}

// ---------------- feature-chunked CSR aggregation ------------------------------
// grid = (N_NODES/8, F/128); warp = one node x one 128-float feature chunk.
// mode 1: single fp16 -> outA (feeds next GEMM A-side)
// mode 2: fp16 hi/lo pair -> outHi/outLo (layer 3, feeds out-stage W-side)
__global__ __launch_bounds__(256)
void agg_kernel(const float* __restrict__ Z, const float* __restrict__ bias,
                __half* __restrict__ outA,
                __half* __restrict__ outHi, __half* __restrict__ outLo,
                int F, int mode) {
    int node = blockIdx.x * 8 + (threadIdx.x >> 5);
    int lane = threadIdx.x & 31;
    int chunk = blockIdx.y;
    int nvec = F >> 2;                  // float4 per row
    int col = chunk * 32 + lane;        // float4 column index

    float4 acc = make_float4(0.f, 0.f, 0.f, 0.f);
    int beg = g_rowptr[node], end = g_rowptr[node + 1];
    const float4* Z4 = (const float4*)Z;
    for (int e = beg; e < end; ++e) {
        int s = g_esrc[e];
        float w = g_ns[s];
        float4 z = Z4[(size_t)s * nvec + col];
        acc.x = fmaf(w, z.x, acc.x);
        acc.y = fmaf(w, z.y, acc.y);
        acc.z = fmaf(w, z.z, acc.z);
        acc.w = fmaf(w, z.w, acc.w);
    }
    float ndv = g_nd[node];
    float4 b = ((const float4*)bias)[col];
    float4 r;
    r.x = fmaxf(fmaf(ndv, acc.x, b.x), 0.f);
    r.y = fmaxf(fmaf(ndv, acc.y, b.y), 0.f);
    r.z = fmaxf(fmaf(ndv, acc.z, b.z), 0.f);
    r.w = fmaxf(fmaf(ndv, acc.w, b.w), 0.f);
    if (mode == 1) {
        uint2 u;
        u.x = pack_h2(r.x, r.y);
        u.y = pack_h2(r.z, r.w);
        ((uint2*)outA)[(size_t)node * nvec + col] = u;
    } else {
        __half hx = __float2half_rn(r.x), hy = __float2half_rn(r.y);
        __half hz = __float2half_rn(r.z), hw = __float2half_rn(r.w);
        uint2 h, l;
        h.x = pack_h2(__half2float(hx), __half2float(hy));
        h.y = pack_h2(__half2float(hz), __half2float(hw));
        l.x = pack_h2(r.x - __half2float(hx), r.y - __half2float(hy));
        l.y = pack_h2(r.z - __half2float(hz), r.w - __half2float(hw));
        ((uint2*)outHi)[(size_t)node * nvec + col] = h;
        ((uint2*)outLo)[(size_t)node * nvec + col] = l;
    }
}

// ---------------- launch --------------------------------------------------------
extern "C" void kernel_launch(void* const* d_in, const int* in_sizes, int n_in,
                              void* d_out, int out_size) {
    const float* x    = (const float*)d_in[0];
    const int*   src  = (const int*)d_in[1];
    const int*   dst  = (const int*)d_in[2];
    const int*   xidx = (const int*)d_in[3];
    const int*   cidx = (const int*)d_in[4];
    const float* W1   = (const float*)d_in[5];
    const float* b1   = (const float*)d_in[6];
    const float* W2   = (const float*)d_in[7];
    const float* b2   = (const float*)d_in[8];
    const float* W3   = (const float*)d_in[9];
    const float* b3   = (const float*)d_in[10];
    const float* Wp   = (const float*)d_in[11];
    const float* bp   = (const float*)d_in[12];
    const float* emb  = (const float*)d_in[13];
    float* out = (float*)d_out;

    static int smem_set = 0;
    if (!smem_set) {
        cudaFuncSetAttribute(gemm_mma_kernel<GK, false>,
                             cudaFuncAttributeMaxDynamicSharedMemorySize, GEMM_SMEM);
        cudaFuncSetAttribute(gemm_mma_kernel<OUT_F, true>,
                             cudaFuncAttributeMaxDynamicSharedMemorySize, GEMM_SMEM);
        smem_set = 1;
    }

    float* Zb;
    __half *A, *W1hi, *W1lo, *W2hi, *W2lo, *W3hi, *W3lo, *Gf, *H3hi, *H3lo, *Ehi, *Elo;
    cudaGetSymbolAddress((void**)&Zb, g_Z);
    cudaGetSymbolAddress((void**)&A, g_A);
    cudaGetSymbolAddress((void**)&W1hi, g_W1hi);
    cudaGetSymbolAddress((void**)&W1lo, g_W1lo);
    cudaGetSymbolAddress((void**)&W2hi, g_W2hi);
    cudaGetSymbolAddress((void**)&W2lo, g_W2lo);
    cudaGetSymbolAddress((void**)&W3hi, g_W3hi);
    cudaGetSymbolAddress((void**)&W3lo, g_W3lo);
    cudaGetSymbolAddress((void**)&Gf, g_Gf);
    cudaGetSymbolAddress((void**)&H3hi, g_H3hi);
    cudaGetSymbolAddress((void**)&H3lo, g_H3lo);
    cudaGetSymbolAddress((void**)&Ehi, g_Ehi);
    cudaGetSymbolAddress((void**)&Elo, g_Elo);

    const int MB = (N_NODES + 127) / 128;   // 391

    // GEMM L1 at launch index 3 (ncu capture slot)
    conv_x_kernel<<<512, 256>>>(x);                                     // 0
    wprep_kernel<<<256, 256>>>(W1, W1hi, W1lo, GK, HID);                // 1
    wprep_kernel<<<256, 256>>>(W2, W2hi, W2lo, GK, HID);                // 2
    gemm_mma_kernel<GK, false><<<dim3(HID / 128, MB), 256, GEMM_SMEM>>>(// 3  <- ncu
        A, W1hi, W1lo, Zb, N_NODES, HID);
    wprep_kernel<<<128, 256>>>(W3, W3hi, W3lo, GK, OUT_F);              // 4
    gmat_kernel<<<N_C, 256>>>(emb, cidx, Wp, bp);                       // 5

    // graph preprocessing (needed before first agg)
    zero_deg_kernel<<<196, 256>>>();
    hist_kernel<<<512, 256>>>(src, dst);
    norm_kernel<<<196, 256>>>();
    scan1_kernel<<<SCAN_BLOCKS, 256>>>();
    scan2_kernel<<<1, 256>>>();
    scan3_kernel<<<SCAN_BLOCKS, 256>>>();
    fill_kernel<<<512, 256>>>(src, dst);

    // Layer 1 aggregation -> single fp16 activations
    agg_kernel<<<dim3(N_NODES / 8, HID / 128), 256>>>(Zb, b1, A, nullptr, nullptr, HID, 1);

    // Layer 2
    gemm_mma_kernel<GK, false><<<dim3(HID / 128, MB), 256, GEMM_SMEM>>>(
        A, W2hi, W2lo, Zb, N_NODES, HID);
    agg_kernel<<<dim3(N_NODES / 8, HID / 128), 256>>>(Zb, b2, A, nullptr, nullptr, HID, 1);

    // Layer 3 (N = 256): agg emits fp16 hi/lo pair (h3, 22-bit accurate)
    gemm_mma_kernel<GK, false><<<dim3(OUT_F / 128, MB), 256, GEMM_SMEM>>>(
        A, W3hi, W3lo, Zb, N_NODES, OUT_F);
    agg_kernel<<<dim3(N_NODES / 8, OUT_F / 128), 256>>>(Zb, b3, nullptr, H3hi, H3lo, OUT_F, 2);

    // dense pre-gather of selected encodings (hi/lo)
    enc_gather_kernel<<<(N_SEL * 32) / 256, 256>>>(xidx);

    // out = G @ E^T + t  — M=1024 (G, single fp16), N=8192 (E hi/lo), K=256
    gemm_mma_kernel<OUT_F, true><<<dim3(N_SEL / 128, N_C / 128), 256, GEMM_SMEM>>>(
        Gf, Ehi, Elo, out, N_C, N_SEL);
}

// round 14
// speedup vs baseline: 1.8412x; 1.2072x over previous
#include <cuda_runtime.h>
#include <cuda_fp16.h>
#include <math.h>
#include <stdint.h>

#define N_NODES 50000
#define N_EDGES 400000
#define IN_F    512
#define HID     512
#define OUT_F   256
#define N_SEL   8192
#define N_C     1024
#define N_DIM   128
#define GK      512        // K of the three big GEMMs

// ---------------- scratch (device globals) ----------------------------------
__device__ float   g_Z  [(size_t)N_NODES * HID];     // GEMM output (pre-agg)
__device__ __half  g_A  [(size_t)N_NODES * HID];     // activations, single fp16
__device__ __half  g_W1 [HID * GK];
__device__ __half  g_W2 [HID * GK];
__device__ __half  g_W3 [OUT_F * GK];
__device__ __half  g_H3hi[(size_t)N_NODES * OUT_F], g_H3lo[(size_t)N_NODES * OUT_F];
__device__ __half  g_Gf [N_C * OUT_F];               // G single fp16
__device__ __half  g_Ehi[(size_t)N_SEL * OUT_F], g_Elo[(size_t)N_SEL * OUT_F];
__device__ float   g_t[N_C];
__device__ float g_ns[N_NODES], g_nd[N_NODES];
__device__ int   g_deg_out[N_NODES], g_deg_in[N_NODES];
__device__ int   g_rowptr[N_NODES + 1], g_cursor[N_NODES], g_esrc[N_EDGES];
__device__ int   g_blockSums[256];

#define SCAN_BLOCKS 196   // 196*256 = 50176 >= N_NODES

// ---------------- low-level helpers ------------------------------------------
__device__ __forceinline__ uint32_t smem_u32(const void* p) {
    uint32_t a;
    asm("{ .reg .u64 t; cvta.to.shared.u64 t, %1; cvt.u32.u64 %0, t; }" : "=r"(a) : "l"(p));
    return a;
}
__device__ __forceinline__ void ldm_x4(uint32_t* r, uint32_t addr) {
    asm volatile("ldmatrix.sync.aligned.m8n8.x4.shared.b16 {%0,%1,%2,%3}, [%4];"
        : "=r"(r[0]), "=r"(r[1]), "=r"(r[2]), "=r"(r[3]) : "r"(addr));
}
__device__ __forceinline__ void mma16816(float* c, const uint32_t* a, const uint32_t* b) {
    asm volatile("mma.sync.aligned.m16n8k16.row.col.f32.f16.f16.f32 "
        "{%0,%1,%2,%3}, {%4,%5,%6,%7}, {%8,%9}, {%0,%1,%2,%3};"
        : "+f"(c[0]), "+f"(c[1]), "+f"(c[2]), "+f"(c[3])
        : "r"(a[0]), "r"(a[1]), "r"(a[2]), "r"(a[3]), "r"(b[0]), "r"(b[1]));
}
__device__ __forceinline__ void cp16(uint32_t saddr, const void* g) {
    asm volatile("cp.async.cg.shared.global [%0], [%1], 16;" :: "r"(saddr), "l"(g));
}
#define CP_COMMIT() asm volatile("cp.async.commit_group;" ::: "memory")
#define CP_WAIT(n)  asm volatile("cp.async.wait_group %0;" :: "n"(n) : "memory")

__device__ __forceinline__ uint32_t pack_h2(float a, float b) {
    __half2 h = __floats2half2_rn(a, b);
    return *(uint32_t*)&h;
}

// ---------------- graph preprocessing ----------------------------------------
__global__ void zero_deg_kernel() {
    int i = blockIdx.x * blockDim.x + threadIdx.x;
    for (; i < N_NODES; i += gridDim.x * blockDim.x) { g_deg_out[i] = 0; g_deg_in[i] = 0; }
}
__global__ void hist_kernel(const int* __restrict__ src, const int* __restrict__ dst) {
    int i = blockIdx.x * blockDim.x + threadIdx.x;
    for (; i < N_EDGES; i += gridDim.x * blockDim.x) {
        atomicAdd(&g_deg_out[src[i]], 1);
        atomicAdd(&g_deg_in[dst[i]], 1);
    }
}
__global__ void norm_kernel() {
    int i = blockIdx.x * blockDim.x + threadIdx.x;
    for (; i < N_NODES; i += gridDim.x * blockDim.x) {
        int dout = g_deg_out[i], din = g_deg_in[i];
        g_ns[i] = dout > 0 ? rsqrtf((float)dout) : 0.0f;
        g_nd[i] = din  > 0 ? rsqrtf((float)din)  : 0.0f;
    }
}
__global__ void scan1_kernel() {
    __shared__ int sh[256];
    int b = blockIdx.x, t = threadIdx.x;
    int i = b * 256 + t;
    sh[t] = (i < N_NODES) ? g_deg_in[i] : 0;
    __syncthreads();
    #pragma unroll
    for (int off = 128; off > 0; off >>= 1) {
        if (t < off) sh[t] += sh[t + off];
        __syncthreads();
    }
    if (t == 0) g_blockSums[b] = sh[0];
}
__global__ void scan2_kernel() {
    __shared__ int sh[256];
    int t = threadIdx.x;
    int v = (t < SCAN_BLOCKS) ? g_blockSums[t] : 0;
    sh[t] = v;
    __syncthreads();
    #pragma unroll
    for (int off = 1; off < 256; off <<= 1) {
        int x = (t >= off) ? sh[t - off] : 0;
        __syncthreads();
        sh[t] += x;
        __syncthreads();
    }
    if (t < SCAN_BLOCKS) g_blockSums[t] = sh[t] - v;
    if (t == 255) g_rowptr[N_NODES] = sh[255];
}
__global__ void scan3_kernel() {
    __shared__ int sh[256];
    int b = blockIdx.x, t = threadIdx.x;
    int i = b * 256 + t;
    int v = (i < N_NODES) ? g_deg_in[i] : 0;
    sh[t] = v;
    __syncthreads();
    #pragma unroll
    for (int off = 1; off < 256; off <<= 1) {
        int x = (t >= off) ? sh[t - off] : 0;
        __syncthreads();
        sh[t] += x;
        __syncthreads();
    }
    if (i < N_NODES) {
        int excl = g_blockSums[b] + sh[t] - v;
        g_rowptr[i] = excl;
        g_cursor[i] = excl;
    }
}
__global__ void fill_kernel(const int* __restrict__ src, const int* __restrict__ dst) {
    int i = blockIdx.x * blockDim.x + threadIdx.x;
    for (; i < N_EDGES; i += gridDim.x * blockDim.x) {
        int p = atomicAdd(&g_cursor[dst[i]], 1);
        g_esrc[p] = src[i];
    }
}

// ---------------- data prep ----------------------------------------------------
// x (fp32) -> single fp16 activations
__global__ void conv_x_kernel(const float* __restrict__ x) {
    const float4* x4 = (const float4*)x;
    uint2* a2 = (uint2*)g_A;
    size_t total = (size_t)N_NODES * IN_F / 4;
    for (size_t i = blockIdx.x * blockDim.x + threadIdx.x; i < total;
         i += (size_t)gridDim.x * blockDim.x) {
        float4 v = x4[i];
        uint2 u;
        u.x = pack_h2(v.x, v.y);
        u.y = pack_h2(v.z, v.w);
        a2[i] = u;
    }
}

// W [K, N] row-major -> W^T single fp16 stored [N, K]
__global__ void wprep_kernel(const float* __restrict__ W, __half* __restrict__ Wt,
                             int Kd, int Nd) {
    int total = Kd * Nd;
    for (int idx = blockIdx.x * blockDim.x + threadIdx.x; idx < total;
         idx += gridDim.x * blockDim.x) {
        int n = idx / Kd, k = idx - n * Kd;
        Wt[idx] = __float2half_rn(W[(size_t)k * Nd + n]);
    }
}

// G[c,f] = emb[cidx[c]] . Wp[f,:]; t[c] = emb_c . bp   (G single fp16)
__global__ __launch_bounds__(256)
void gmat_kernel(const float* __restrict__ emb, const int* __restrict__ cidx,
                 const float* __restrict__ Wp, const float* __restrict__ bp) {
    __shared__ float e[N_DIM];
    __shared__ float tp[N_DIM];
    int c = blockIdx.x;
    int t = threadIdx.x;
    int row = cidx[c];
    if (t < N_DIM) {
        float ev = emb[(size_t)row * N_DIM + t];
        e[t] = ev;
        tp[t] = ev * bp[t];
    }
    __syncthreads();
    const float* w = Wp + (size_t)t * N_DIM;
    float a0 = 0.f, a1 = 0.f, a2 = 0.f, a3 = 0.f;
    #pragma unroll 8
    for (int d = 0; d < N_DIM; d += 4) {
        a0 = fmaf(e[d + 0], w[d + 0], a0);
        a1 = fmaf(e[d + 1], w[d + 1], a1);
        a2 = fmaf(e[d + 2], w[d + 2], a2);
        a3 = fmaf(e[d + 3], w[d + 3], a3);
    }
    float acc = (a0 + a1) + (a2 + a3);
    g_Gf[c * OUT_F + t] = __float2half_rn(acc);
    if (t == 0) {
        float s = 0.f;
        #pragma unroll
        for (int d = 0; d < N_DIM; d++) s += tp[d];
        g_t[c] = s;
    }
}

// dense pre-gather: E(hi/lo) = h3(hi/lo)[xidx]
__global__ __launch_bounds__(256)
void enc_gather_kernel(const int* __restrict__ xidx) {
    int i = blockIdx.x * blockDim.x + threadIdx.x;   // over N_SEL*32
    int s = i >> 5, c = i & 31;                       // 32 uint4 per 256-fp16 row
    int r = xidx[s];
    ((uint4*)g_Ehi)[(size_t)s * 32 + c] = ((const uint4*)g_H3hi)[(size_t)r * 32 + c];
    ((uint4*)g_Elo)[(size_t)s * 32 + c] = ((const uint4*)g_H3lo)[(size_t)r * 32 + c];
}

// ---------------- GEMM common ---------------------------------------------------
#define SROW 80                        // bytes per smem row (32 fp16 data + pad)
#define TILE_BYTES (128 * SROW)        // 10240 B

// 128x32 fp16 tile loader, sequential rows (clamped)
__device__ __forceinline__ void issue_rows(const __half* __restrict__ G,
                                           int row0, int rmax, int rstride,
                                           uint32_t sbase, int k0, int tid) {
    const char* g = (const char*)G;
    #pragma unroll
    for (int i = 0; i < 2; i++) {
        int v = tid + 256 * i;            // 0..511
        int r = v >> 2, c = v & 3;        // 128 rows x 4 x 16B
        int gr = row0 + r;
        gr = gr < rmax ? gr : rmax - 1;
        cp16(sbase + r * SROW + c * 16,
             g + ((size_t)gr * rstride + k0) * 2 + c * 16);
    }
}

// ============ 1-term node GEMM: C = A[M,K] @ (W[N,K])^T, fp32 acc ===============
#define G1_STAGE (2 * TILE_BYTES)      // 20480 B (A, W)
#define G1_SMEM  (2 * G1_STAGE)        // 40960 B

template <int KDIM>
__global__ __launch_bounds__(256, 2)
void gemm1_kernel(const __half* __restrict__ A, const __half* __restrict__ W,
                  float* __restrict__ C, int M, int N) {
    extern __shared__ __align__(16) char sm[];
    uint32_t u0 = smem_u32(sm);

    int tid = threadIdx.x;
    int wid = tid >> 5, lane = tid & 31;
    int tile_m = blockIdx.y * 128, tile_n = blockIdx.x * 128;
    int warp_m = (wid >> 2) * 64;
    int warp_n = (wid & 3) * 32;

    float acc[4][4][4];
    #pragma unroll
    for (int a = 0; a < 4; a++)
        #pragma unroll
        for (int b = 0; b < 4; b++)
            #pragma unroll
            for (int c = 0; c < 4; c++) acc[a][b][c] = 0.0f;

    int a_r  = lane & 15;
    int a_ko = (lane >> 4) << 3;
    int b_g  = lane >> 3, b_i = lane & 7;
    int b_nr = ((b_g >> 1) << 3) + b_i;
    int b_ko = (b_g & 1) << 3;

    const int NCH = KDIM / 32;

    {
        uint32_t st = u0;
        issue_rows(A, tile_m, M, KDIM, st,              0, tid);
        issue_rows(W, tile_n, N, KDIM, st + TILE_BYTES, 0, tid);
        CP_COMMIT();
    }

    for (int ch = 0; ch < NCH; ch++) {
        CP_WAIT(0);
        __syncthreads();

        if (ch + 1 < NCH) {
            uint32_t st = u0 + ((ch + 1) & 1) * G1_STAGE;
            int k0g = (ch + 1) * 32;
            issue_rows(A, tile_m, M, KDIM, st,              k0g, tid);
            issue_rows(W, tile_n, N, KDIM, st + TILE_BYTES, k0g, tid);
            CP_COMMIT();
        }

        uint32_t stc = u0 + (ch & 1) * G1_STAGE;
        uint32_t uA = stc, uW = stc + TILE_BYTES;

        #pragma unroll
        for (int ks = 0; ks < 2; ks++) {
            int k0 = ks * 16;
            uint32_t bh[2][4], af[4][4];
            #pragma unroll
            for (int t = 0; t < 2; t++) {
                uint32_t noff = (uint32_t)(warp_n + t * 16 + b_nr) * SROW + (k0 + b_ko) * 2;
                ldm_x4(bh[t], uW + noff);
            }
            #pragma unroll
            for (int mt = 0; mt < 4; mt++) {
                uint32_t moff = (uint32_t)(warp_m + mt * 16 + a_r) * SROW + (k0 + a_ko) * 2;
                ldm_x4(af[mt], uA + moff);
            }
            #pragma unroll
            for (int mt = 0; mt < 4; mt++)
                #pragma unroll
                for (int nt = 0; nt < 4; nt++)
                    mma16816(acc[mt][nt], af[mt], &bh[nt >> 1][(nt & 1) * 2]);
        }
    }

    int er = lane >> 2, ec = (lane & 3) << 1;
    #pragma unroll
    for (int mt = 0; mt < 4; mt++) {
        #pragma unroll
        for (int nt = 0; nt < 4; nt++) {
            int r0 = tile_m + warp_m + mt * 16 + er;
            int c0 = tile_n + warp_n + nt * 8 + ec;
            if (r0 < M)
                *(float2*)&C[(size_t)r0 * N + c0] = make_float2(acc[mt][nt][0], acc[mt][nt][1]);
            if (r0 + 8 < M)
                *(float2*)&C[(size_t)(r0 + 8) * N + c0] = make_float2(acc[mt][nt][2], acc[mt][nt][3]);
        }
    }
}

// ============ 2-term out GEMM: C = G[M,K] @ ((Ehi+Elo)[N,K])^T + t ==============
#define G2_STAGE (3 * TILE_BYTES)      // 30720 B (G, Ehi, Elo)
#define G2_SMEM  (2 * G2_STAGE)        // 61440 B

__global__ __launch_bounds__(256, 2)
void gemm2_kernel(const __half* __restrict__ A,
                  const __half* __restrict__ Whi, const __half* __restrict__ Wlo,
                  float* __restrict__ C, int M, int N) {
    extern __shared__ __align__(16) char sm[];
    uint32_t u0 = smem_u32(sm);
    const int KDIM = OUT_F;

    int tid = threadIdx.x;
    int wid = tid >> 5, lane = tid & 31;
    int tile_m = blockIdx.y * 128, tile_n = blockIdx.x * 128;
    int warp_m = (wid >> 2) * 64;
    int warp_n = (wid & 3) * 32;

    float acc[4][4][4];
    #pragma unroll
    for (int a = 0; a < 4; a++)
        #pragma unroll
        for (int b = 0; b < 4; b++)
            #pragma unroll
            for (int c = 0; c < 4; c++) acc[a][b][c] = 0.0f;

    int a_r  = lane & 15;
    int a_ko = (lane >> 4) << 3;
    int b_g  = lane >> 3, b_i = lane & 7;
    int b_nr = ((b_g >> 1) << 3) + b_i;
    int b_ko = (b_g & 1) << 3;

    const int NCH = KDIM / 32;

    {
        uint32_t st = u0;
        issue_rows(A,   tile_m, M, KDIM, st,                  0, tid);
        issue_rows(Whi, tile_n, N, KDIM, st + TILE_BYTES,     0, tid);
        issue_rows(Wlo, tile_n, N, KDIM, st + 2 * TILE_BYTES, 0, tid);
        CP_COMMIT();
    }

    for (int ch = 0; ch < NCH; ch++) {
        CP_WAIT(0);
        __syncthreads();

        if (ch + 1 < NCH) {
            uint32_t st = u0 + ((ch + 1) & 1) * G2_STAGE;
            int k0g = (ch + 1) * 32;
            issue_rows(A,   tile_m, M, KDIM, st,                  k0g, tid);
            issue_rows(Whi, tile_n, N, KDIM, st + TILE_BYTES,     k0g, tid);
            issue_rows(Wlo, tile_n, N, KDIM, st + 2 * TILE_BYTES, k0g, tid);
            CP_COMMIT();
        }

        uint32_t stc = u0 + (ch & 1) * G2_STAGE;
        uint32_t uA = stc;
        uint32_t uWH = stc + TILE_BYTES, uWL = stc + 2 * TILE_BYTES;

        #pragma unroll
        for (int ks = 0; ks < 2; ks++) {
            int k0 = ks * 16;
            uint32_t bh[2][4], bl[2][4], af[4][4];
            #pragma unroll
            for (int t = 0; t < 2; t++) {
                uint32_t noff = (uint32_t)(warp_n + t * 16 + b_nr) * SROW + (k0 + b_ko) * 2;
                ldm_x4(bh[t], uWH + noff);
                ldm_x4(bl[t], uWL + noff);
            }
            #pragma unroll
            for (int mt = 0; mt < 4; mt++) {
                uint32_t moff = (uint32_t)(warp_m + mt * 16 + a_r) * SROW + (k0 + a_ko) * 2;
                ldm_x4(af[mt], uA + moff);
            }
            #pragma unroll
            for (int mt = 0; mt < 4; mt++)
                #pragma unroll
                for (int nt = 0; nt < 4; nt++) {
                    mma16816(acc[mt][nt], af[mt], &bh[nt >> 1][(nt & 1) * 2]);
                    mma16816(acc[mt][nt], af[mt], &bl[nt >> 1][(nt & 1) * 2]);
                }
        }
    }

    int er = lane >> 2, ec = (lane & 3) << 1;
    #pragma unroll
    for (int mt = 0; mt < 4; mt++) {
        #pragma unroll
        for (int nt = 0; nt < 4; nt++) {
            int r0 = tile_m + warp_m + mt * 16 + er;
            int c0 = tile_n + warp_n + nt * 8 + ec;
            float t0 = g_t[r0], t1 = g_t[r0 + 8];
            *(float2*)&C[(size_t)r0 * N + c0] =
                make_float2(acc[mt][nt][0] + t0, acc[mt][nt][1] + t0);
            *(float2*)&C[(size_t)(r0 + 8) * N + c0] =
                make_float2(acc[mt][nt][2] + t1, acc[mt][nt][3] + t1);
        }
    }
}

// ---------------- feature-chunked CSR aggregation ------------------------------
// mode 1: single fp16 -> outA; mode 2: fp16 hi/lo pair -> outHi/outLo (layer 3)
__global__ __launch_bounds__(256)
void agg_kernel(const float* __restrict__ Z, const float* __restrict__ bias,
                __half* __restrict__ outA,
                __half* __restrict__ outHi, __half* __restrict__ outLo,
                int F, int mode) {
    int node = blockIdx.x * 8 + (threadIdx.x >> 5);
    int lane = threadIdx.x & 31;
    int chunk = blockIdx.y;
    int nvec = F >> 2;                  // float4 per row
    int col = chunk * 32 + lane;        // float4 column index

    float4 acc = make_float4(0.f, 0.f, 0.f, 0.f);
    int beg = g_rowptr[node], end = g_rowptr[node + 1];
    const float4* Z4 = (const float4*)Z;
    for (int e = beg; e < end; ++e) {
        int s = g_esrc[e];
        float w = g_ns[s];
        float4 z = Z4[(size_t)s * nvec + col];
        acc.x = fmaf(w, z.x, acc.x);
        acc.y = fmaf(w, z.y, acc.y);
        acc.z = fmaf(w, z.z, acc.z);
        acc.w = fmaf(w, z.w, acc.w);
    }
    float ndv = g_nd[node];
    float4 b = ((const float4*)bias)[col];
    float4 r;
    r.x = fmaxf(fmaf(ndv, acc.x, b.x), 0.f);
    r.y = fmaxf(fmaf(ndv, acc.y, b.y), 0.f);
    r.z = fmaxf(fmaf(ndv, acc.z, b.z), 0.f);
    r.w = fmaxf(fmaf(ndv, acc.w, b.w), 0.f);
    if (mode == 1) {
        uint2 u;
        u.x = pack_h2(r.x, r.y);
        u.y = pack_h2(r.z, r.w);
        ((uint2*)outA)[(size_t)node * nvec + col] = u;
    } else {
        __half hx = __float2half_rn(r.x), hy = __float2half_rn(r.y);
        __half hz = __float2half_rn(r.z), hw = __float2half_rn(r.w);
        uint2 h, l;
        h.x = pack_h2(__half2float(hx), __half2float(hy));
        h.y = pack_h2(__half2float(hz), __half2float(hw));
        l.x = pack_h2(r.x - __half2float(hx), r.y - __half2float(hy));
        l.y = pack_h2(r.z - __half2float(hz), r.w - __half2float(hw));
        ((uint2*)outHi)[(size_t)node * nvec + col] = h;
        ((uint2*)outLo)[(size_t)node * nvec + col] = l;
    }
}

// ---------------- launch --------------------------------------------------------
extern "C" void kernel_launch(void* const* d_in, const int* in_sizes, int n_in,
                              void* d_out, int out_size) {
    const float* x    = (const float*)d_in[0];
    const int*   src  = (const int*)d_in[1];
    const int*   dst  = (const int*)d_in[2];
    const int*   xidx = (const int*)d_in[3];
    const int*   cidx = (const int*)d_in[4];
    const float* W1   = (const float*)d_in[5];
    const float* b1   = (const float*)d_in[6];
    const float* W2   = (const float*)d_in[7];
    const float* b2   = (const float*)d_in[8];
    const float* W3   = (const float*)d_in[9];
    const float* b3   = (const float*)d_in[10];
    const float* Wp   = (const float*)d_in[11];
    const float* bp   = (const float*)d_in[12];
    const float* emb  = (const float*)d_in[13];
    float* out = (float*)d_out;

    static int smem_set = 0;
    if (!smem_set) {
        cudaFuncSetAttribute(gemm1_kernel<GK>,
                             cudaFuncAttributeMaxDynamicSharedMemorySize, G1_SMEM);
        cudaFuncSetAttribute(gemm2_kernel,
                             cudaFuncAttributeMaxDynamicSharedMemorySize, G2_SMEM);
        smem_set = 1;
    }

    float* Zb;
    __half *A, *W1t, *W2t, *W3t, *Gf, *H3hi, *H3lo, *Ehi, *Elo;
    cudaGetSymbolAddress((void**)&Zb, g_Z);
    cudaGetSymbolAddress((void**)&A, g_A);
    cudaGetSymbolAddress((void**)&W1t, g_W1);
    cudaGetSymbolAddress((void**)&W2t, g_W2);
    cudaGetSymbolAddress((void**)&W3t, g_W3);
    cudaGetSymbolAddress((void**)&Gf, g_Gf);
    cudaGetSymbolAddress((void**)&H3hi, g_H3hi);
    cudaGetSymbolAddress((void**)&H3lo, g_H3lo);
    cudaGetSymbolAddress((void**)&Ehi, g_Ehi);
    cudaGetSymbolAddress((void**)&Elo, g_Elo);

    const int MB = (N_NODES + 127) / 128;   // 391

    // GEMM L1 at launch index 3 (ncu capture slot)
    conv_x_kernel<<<512, 256>>>(x);                                  // 0
    wprep_kernel<<<256, 256>>>(W1, W1t, GK, HID);                    // 1
    wprep_kernel<<<256, 256>>>(W2, W2t, GK, HID);                    // 2
    gemm1_kernel<GK><<<dim3(HID / 128, MB), 256, G1_SMEM>>>(         // 3  <- ncu
        A, W1t, Zb, N_NODES, HID);
    wprep_kernel<<<128, 256>>>(W3, W3t, GK, OUT_F);                  // 4
    gmat_kernel<<<N_C, 256>>>(emb, cidx, Wp, bp);                    // 5

    // graph preprocessing (needed before first agg)
    zero_deg_kernel<<<196, 256>>>();
    hist_kernel<<<512, 256>>>(src, dst);
    norm_kernel<<<196, 256>>>();
    scan1_kernel<<<SCAN_BLOCKS, 256>>>();
    scan2_kernel<<<1, 256>>>();
    scan3_kernel<<<SCAN_BLOCKS, 256>>>();
    fill_kernel<<<512, 256>>>(src, dst);

    // Layer 1 aggregation -> single fp16 activations
    agg_kernel<<<dim3(N_NODES / 8, HID / 128), 256>>>(Zb, b1, A, nullptr, nullptr, HID, 1);

    // Layer 2
    gemm1_kernel<GK><<<dim3(HID / 128, MB), 256, G1_SMEM>>>(A, W2t, Zb, N_NODES, HID);
    agg_kernel<<<dim3(N_NODES / 8, HID / 128), 256>>>(Zb, b2, A, nullptr, nullptr, HID, 1);

    // Layer 3 (N = 256): agg emits fp16 hi/lo pair (h3, 22-bit accurate)
    gemm1_kernel<GK><<<dim3(OUT_F / 128, MB), 256, G1_SMEM>>>(A, W3t, Zb, N_NODES, OUT_F);
    agg_kernel<<<dim3(N_NODES / 8, OUT_F / 128), 256>>>(Zb, b3, nullptr, H3hi, H3lo, OUT_F, 2);

    // dense pre-gather of selected encodings (hi/lo)
    enc_gather_kernel<<<(N_SEL * 32) / 256, 256>>>(xidx);

    // out = G @ E^T + t  — M=1024 (G single fp16), N=8192 (E hi/lo), K=256
    gemm2_kernel<<<dim3(N_SEL / 128, N_C / 128), 256, G2_SMEM>>>(
        Gf, Ehi, Elo, out, N_C, N_SEL);
}

// round 15
// speedup vs baseline: 2.0466x; 1.1116x over previous
#include <cuda_runtime.h>
#include <cuda_fp16.h>
#include <math.h>
#include <stdint.h>

#define N_NODES 50000
#define N_EDGES 400000
#define IN_F    512
#define HID     512
#define OUT_F   256
#define N_SEL   8192
#define N_C     1024
#define N_DIM   128
#define GK      512        // K of the three big GEMMs

// ---------------- scratch (device globals) ----------------------------------
__device__ __half  g_Z  [(size_t)N_NODES * HID];     // GEMM output (pre-agg), fp16
__device__ __half  g_A  [(size_t)N_NODES * HID];     // activations, single fp16
__device__ __half  g_W1 [HID * GK];
__device__ __half  g_W2 [HID * GK];
__device__ __half  g_W3 [OUT_F * GK];
__device__ __half  g_H3hi[(size_t)N_NODES * OUT_F], g_H3lo[(size_t)N_NODES * OUT_F];
__device__ __half  g_Gf [N_C * OUT_F];               // G single fp16
__device__ __half  g_Ehi[(size_t)N_SEL * OUT_F], g_Elo[(size_t)N_SEL * OUT_F];
__device__ float   g_t[N_C];
__device__ float g_ns[N_NODES], g_nd[N_NODES];
__device__ int   g_deg_out[N_NODES], g_deg_in[N_NODES];
__device__ int   g_rowptr[N_NODES + 1], g_cursor[N_NODES], g_esrc[N_EDGES];
__device__ int   g_blockSums[256];

#define SCAN_BLOCKS 196   // 196*256 = 50176 >= N_NODES

// ---------------- low-level helpers ------------------------------------------
__device__ __forceinline__ uint32_t smem_u32(const void* p) {
    uint32_t a;
    asm("{ .reg .u64 t; cvta.to.shared.u64 t, %1; cvt.u32.u64 %0, t; }" : "=r"(a) : "l"(p));
    return a;
}
__device__ __forceinline__ void ldm_x4(uint32_t* r, uint32_t addr) {
    asm volatile("ldmatrix.sync.aligned.m8n8.x4.shared.b16 {%0,%1,%2,%3}, [%4];"
        : "=r"(r[0]), "=r"(r[1]), "=r"(r[2]), "=r"(r[3]) : "r"(addr));
}
__device__ __forceinline__ void mma16816(float* c, const uint32_t* a, const uint32_t* b) {
    asm volatile("mma.sync.aligned.m16n8k16.row.col.f32.f16.f16.f32 "
        "{%0,%1,%2,%3}, {%4,%5,%6,%7}, {%8,%9}, {%0,%1,%2,%3};"
        : "+f"(c[0]), "+f"(c[1]), "+f"(c[2]), "+f"(c[3])
        : "r"(a[0]), "r"(a[1]), "r"(a[2]), "r"(a[3]), "r"(b[0]), "r"(b[1]));
}
__device__ __forceinline__ void cp16(uint32_t saddr, const void* g) {
    asm volatile("cp.async.cg.shared.global [%0], [%1], 16;" :: "r"(saddr), "l"(g));
}
#define CP_COMMIT() asm volatile("cp.async.commit_group;" ::: "memory")
#define CP_WAIT(n)  asm volatile("cp.async.wait_group %0;" :: "n"(n) : "memory")

__device__ __forceinline__ uint32_t pack_h2(float a, float b) {
    __half2 h = __floats2half2_rn(a, b);
    return *(uint32_t*)&h;
}

// ---------------- graph preprocessing ----------------------------------------
__global__ void zero_deg_kernel() {
    int i = blockIdx.x * blockDim.x + threadIdx.x;
    for (; i < N_NODES; i += gridDim.x * blockDim.x) { g_deg_out[i] = 0; g_deg_in[i] = 0; }
}
__global__ void hist_kernel(const int* __restrict__ src, const int* __restrict__ dst) {
    int i = blockIdx.x * blockDim.x + threadIdx.x;
    for (; i < N_EDGES; i += gridDim.x * blockDim.x) {
        atomicAdd(&g_deg_out[src[i]], 1);
        atomicAdd(&g_deg_in[dst[i]], 1);
    }
}
__global__ void norm_kernel() {
    int i = blockIdx.x * blockDim.x + threadIdx.x;
    for (; i < N_NODES; i += gridDim.x * blockDim.x) {
        int dout = g_deg_out[i], din = g_deg_in[i];
        g_ns[i] = dout > 0 ? rsqrtf((float)dout) : 0.0f;
        g_nd[i] = din  > 0 ? rsqrtf((float)din)  : 0.0f;
    }
}
__global__ void scan1_kernel() {
    __shared__ int sh[256];
    int b = blockIdx.x, t = threadIdx.x;
    int i = b * 256 + t;
    sh[t] = (i < N_NODES) ? g_deg_in[i] : 0;
    __syncthreads();
    #pragma unroll
    for (int off = 128; off > 0; off >>= 1) {
        if (t < off) sh[t] += sh[t + off];
        __syncthreads();
    }
    if (t == 0) g_blockSums[b] = sh[0];
}
__global__ void scan2_kernel() {
    __shared__ int sh[256];
    int t = threadIdx.x;
    int v = (t < SCAN_BLOCKS) ? g_blockSums[t] : 0;
    sh[t] = v;
    __syncthreads();
    #pragma unroll
    for (int off = 1; off < 256; off <<= 1) {
        int x = (t >= off) ? sh[t - off] : 0;
        __syncthreads();
        sh[t] += x;
        __syncthreads();
    }
    if (t < SCAN_BLOCKS) g_blockSums[t] = sh[t] - v;
    if (t == 255) g_rowptr[N_NODES] = sh[255];
}
__global__ void scan3_kernel() {
    __shared__ int sh[256];
    int b = blockIdx.x, t = threadIdx.x;
    int i = b * 256 + t;
    int v = (i < N_NODES) ? g_deg_in[i] : 0;
    sh[t] = v;
    __syncthreads();
    #pragma unroll
    for (int off = 1; off < 256; off <<= 1) {
        int x = (t >= off) ? sh[t - off] : 0;
        __syncthreads();
        sh[t] += x;
        __syncthreads();
    }
    if (i < N_NODES) {
        int excl = g_blockSums[b] + sh[t] - v;
        g_rowptr[i] = excl;
        g_cursor[i] = excl;
    }
}
__global__ void fill_kernel(const int* __restrict__ src, const int* __restrict__ dst) {
    int i = blockIdx.x * blockDim.x + threadIdx.x;
    for (; i < N_EDGES; i += gridDim.x * blockDim.x) {
        int p = atomicAdd(&g_cursor[dst[i]], 1);
        g_esrc[p] = src[i];
    }
}

// ---------------- data prep ----------------------------------------------------
__global__ void conv_x_kernel(const float* __restrict__ x) {
    const float4* x4 = (const float4*)x;
    uint2* a2 = (uint2*)g_A;
    size_t total = (size_t)N_NODES * IN_F / 4;
    for (size_t i = blockIdx.x * blockDim.x + threadIdx.x; i < total;
         i += (size_t)gridDim.x * blockDim.x) {
        float4 v = x4[i];
        uint2 u;
        u.x = pack_h2(v.x, v.y);
        u.y = pack_h2(v.z, v.w);
        a2[i] = u;
    }
}

// W [K, N] row-major -> W^T single fp16 stored [N, K]
__global__ void wprep_kernel(const float* __restrict__ W, __half* __restrict__ Wt,
                             int Kd, int Nd) {
    int total = Kd * Nd;
    for (int idx = blockIdx.x * blockDim.x + threadIdx.x; idx < total;
         idx += gridDim.x * blockDim.x) {
        int n = idx / Kd, k = idx - n * Kd;
        Wt[idx] = __float2half_rn(W[(size_t)k * Nd + n]);
    }
}

// G[c,f] = emb[cidx[c]] . Wp[f,:]; t[c] = emb_c . bp   (G single fp16)
__global__ __launch_bounds__(256)
void gmat_kernel(const float* __restrict__ emb, const int* __restrict__ cidx,
                 const float* __restrict__ Wp, const float* __restrict__ bp) {
    __shared__ float e[N_DIM];
    __shared__ float tp[N_DIM];
    int c = blockIdx.x;
    int t = threadIdx.x;
    int row = cidx[c];
    if (t < N_DIM) {
        float ev = emb[(size_t)row * N_DIM + t];
        e[t] = ev;
        tp[t] = ev * bp[t];
    }
    __syncthreads();
    const float* w = Wp + (size_t)t * N_DIM;
    float a0 = 0.f, a1 = 0.f, a2 = 0.f, a3 = 0.f;
    #pragma unroll 8
    for (int d = 0; d < N_DIM; d += 4) {
        a0 = fmaf(e[d + 0], w[d + 0], a0);
        a1 = fmaf(e[d + 1], w[d + 1], a1);
        a2 = fmaf(e[d + 2], w[d + 2], a2);
        a3 = fmaf(e[d + 3], w[d + 3], a3);
    }
    float acc = (a0 + a1) + (a2 + a3);
    g_Gf[c * OUT_F + t] = __float2half_rn(acc);
    if (t == 0) {
        float s = 0.f;
        #pragma unroll
        for (int d = 0; d < N_DIM; d++) s += tp[d];
        g_t[c] = s;
    }
}

// dense pre-gather: E(hi/lo) = h3(hi/lo)[xidx]
__global__ __launch_bounds__(256)
void enc_gather_kernel(const int* __restrict__ xidx) {
    int i = blockIdx.x * blockDim.x + threadIdx.x;   // over N_SEL*32
    int s = i >> 5, c = i & 31;                       // 32 uint4 per 256-fp16 row
    int r = xidx[s];
    ((uint4*)g_Ehi)[(size_t)s * 32 + c] = ((const uint4*)g_H3hi)[(size_t)r * 32 + c];
    ((uint4*)g_Elo)[(size_t)s * 32 + c] = ((const uint4*)g_H3lo)[(size_t)r * 32 + c];
}

// ---------------- GEMM common (BK = 64) -----------------------------------------
#define SROW 144                       // 128 B data + 16 pad (16B aligned, conflict-free)
#define TILE_BYTES (128 * SROW)        // 18432 B

// 128x64 fp16 tile loader, sequential rows (clamped); 4 cp16 per thread
__device__ __forceinline__ void issue_rows(const __half* __restrict__ G,
                                           int row0, int rmax, int rstride,
                                           uint32_t sbase, int k0, int tid) {
    const char* g = (const char*)G;
    #pragma unroll
    for (int i = 0; i < 4; i++) {
        int v = tid + 256 * i;            // 0..1023
        int r = v >> 3, c = v & 7;        // 128 rows x 8 x 16B
        int gr = row0 + r;
        gr = gr < rmax ? gr : rmax - 1;
        cp16(sbase + r * SROW + c * 16,
             g + ((size_t)gr * rstride + k0) * 2 + c * 16);
    }
}

// ============ 1-term node GEMM: Z(fp16) = A[M,K] @ (W[N,K])^T ===================
#define G1_STAGE (2 * TILE_BYTES)      // 36864 B (A, W)
#define G1_SMEM  (2 * G1_STAGE)        // 73728 B

template <int KDIM>
__global__ __launch_bounds__(256, 2)
void gemm1_kernel(const __half* __restrict__ A, const __half* __restrict__ W,
                  __half* __restrict__ C, int M, int N) {
    extern __shared__ __align__(16) char sm[];
    uint32_t u0 = smem_u32(sm);

    int tid = threadIdx.x;
    int wid = tid >> 5, lane = tid & 31;
    int tile_m = blockIdx.y * 128, tile_n = blockIdx.x * 128;
    int warp_m = (wid >> 2) * 64;
    int warp_n = (wid & 3) * 32;

    float acc[4][4][4];
    #pragma unroll
    for (int a = 0; a < 4; a++)
        #pragma unroll
        for (int b = 0; b < 4; b++)
            #pragma unroll
            for (int c = 0; c < 4; c++) acc[a][b][c] = 0.0f;

    int a_r  = lane & 15;
    int a_ko = (lane >> 4) << 3;
    int b_g  = lane >> 3, b_i = lane & 7;
    int b_nr = ((b_g >> 1) << 3) + b_i;
    int b_ko = (b_g & 1) << 3;

    const int NCH = KDIM / 64;

    {
        uint32_t st = u0;
        issue_rows(A, tile_m, M, KDIM, st,              0, tid);
        issue_rows(W, tile_n, N, KDIM, st + TILE_BYTES, 0, tid);
        CP_COMMIT();
    }

    for (int ch = 0; ch < NCH; ch++) {
        CP_WAIT(0);
        __syncthreads();

        if (ch + 1 < NCH) {
            uint32_t st = u0 + ((ch + 1) & 1) * G1_STAGE;
            int k0g = (ch + 1) * 64;
            issue_rows(A, tile_m, M, KDIM, st,              k0g, tid);
            issue_rows(W, tile_n, N, KDIM, st + TILE_BYTES, k0g, tid);
            CP_COMMIT();
        }

        uint32_t stc = u0 + (ch & 1) * G1_STAGE;
        uint32_t uA = stc, uW = stc + TILE_BYTES;

        #pragma unroll
        for (int ks = 0; ks < 4; ks++) {
            int k0 = ks * 16;
            uint32_t bh[2][4], af[4][4];
            #pragma unroll
            for (int t = 0; t < 2; t++) {
                uint32_t noff = (uint32_t)(warp_n + t * 16 + b_nr) * SROW + (k0 + b_ko) * 2;
                ldm_x4(bh[t], uW + noff);
            }
            #pragma unroll
            for (int mt = 0; mt < 4; mt++) {
                uint32_t moff = (uint32_t)(warp_m + mt * 16 + a_r) * SROW + (k0 + a_ko) * 2;
                ldm_x4(af[mt], uA + moff);
            }
            #pragma unroll
            for (int mt = 0; mt < 4; mt++)
                #pragma unroll
                for (int nt = 0; nt < 4; nt++)
                    mma16816(acc[mt][nt], af[mt], &bh[nt >> 1][(nt & 1) * 2]);
        }
    }

    int er = lane >> 2, ec = (lane & 3) << 1;
    #pragma unroll
    for (int mt = 0; mt < 4; mt++) {
        #pragma unroll
        for (int nt = 0; nt < 4; nt++) {
            int r0 = tile_m + warp_m + mt * 16 + er;
            int c0 = tile_n + warp_n + nt * 8 + ec;
            uint32_t p0 = pack_h2(acc[mt][nt][0], acc[mt][nt][1]);
            uint32_t p1 = pack_h2(acc[mt][nt][2], acc[mt][nt][3]);
            if (r0 < M)
                *(uint32_t*)&C[(size_t)r0 * N + c0] = p0;
            if (r0 + 8 < M)
                *(uint32_t*)&C[(size_t)(r0 + 8) * N + c0] = p1;
        }
    }
}

// ============ 2-term out GEMM: out = G[M,K] @ ((Ehi+Elo)[N,K])^T + t ============
#define G2_STAGE (3 * TILE_BYTES)      // 55296 B (G, Ehi, Elo)
#define G2_SMEM  (2 * G2_STAGE)        // 110592 B

__global__ __launch_bounds__(256, 2)
void gemm2_kernel(const __half* __restrict__ A,
                  const __half* __restrict__ Whi, const __half* __restrict__ Wlo,
                  float* __restrict__ C, int M, int N) {
    extern __shared__ __align__(16) char sm[];
    uint32_t u0 = smem_u32(sm);
    const int KDIM = OUT_F;

    int tid = threadIdx.x;
    int wid = tid >> 5, lane = tid & 31;
    int tile_m = blockIdx.y * 128, tile_n = blockIdx.x * 128;
    int warp_m = (wid >> 2) * 64;
    int warp_n = (wid & 3) * 32;

    float acc[4][4][4];
    #pragma unroll
    for (int a = 0; a < 4; a++)
        #pragma unroll
        for (int b = 0; b < 4; b++)
            #pragma unroll
            for (int c = 0; c < 4; c++) acc[a][b][c] = 0.0f;

    int a_r  = lane & 15;
    int a_ko = (lane >> 4) << 3;
    int b_g  = lane >> 3, b_i = lane & 7;
    int b_nr = ((b_g >> 1) << 3) + b_i;
    int b_ko = (b_g & 1) << 3;

    const int NCH = KDIM / 64;   // 4

    {
        uint32_t st = u0;
        issue_rows(A,   tile_m, M, KDIM, st,                  0, tid);
        issue_rows(Whi, tile_n, N, KDIM, st + TILE_BYTES,     0, tid);
        issue_rows(Wlo, tile_n, N, KDIM, st + 2 * TILE_BYTES, 0, tid);
        CP_COMMIT();
    }

    for (int ch = 0; ch < NCH; ch++) {
        CP_WAIT(0);
        __syncthreads();

        if (ch + 1 < NCH) {
            uint32_t st = u0 + ((ch + 1) & 1) * G2_STAGE;
            int k0g = (ch + 1) * 64;
            issue_rows(A,   tile_m, M, KDIM, st,                  k0g, tid);
            issue_rows(Whi, tile_n, N, KDIM, st + TILE_BYTES,     k0g, tid);
            issue_rows(Wlo, tile_n, N, KDIM, st + 2 * TILE_BYTES, k0g, tid);
            CP_COMMIT();
        }

        uint32_t stc = u0 + (ch & 1) * G2_STAGE;
        uint32_t uA = stc;
        uint32_t uWH = stc + TILE_BYTES, uWL = stc + 2 * TILE_BYTES;

        #pragma unroll
        for (int ks = 0; ks < 4; ks++) {
            int k0 = ks * 16;
            uint32_t bh[2][4], bl[2][4], af[4][4];
            #pragma unroll
            for (int t = 0; t < 2; t++) {
                uint32_t noff = (uint32_t)(warp_n + t * 16 + b_nr) * SROW + (k0 + b_ko) * 2;
                ldm_x4(bh[t], uWH + noff);
                ldm_x4(bl[t], uWL + noff);
            }
            #pragma unroll
            for (int mt = 0; mt < 4; mt++) {
                uint32_t moff = (uint32_t)(warp_m + mt * 16 + a_r) * SROW + (k0 + a_ko) * 2;
                ldm_x4(af[mt], uA + moff);
            }
            #pragma unroll
            for (int mt = 0; mt < 4; mt++)
                #pragma unroll
                for (int nt = 0; nt < 4; nt++) {
                    mma16816(acc[mt][nt], af[mt], &bh[nt >> 1][(nt & 1) * 2]);
                    mma16816(acc[mt][nt], af[mt], &bl[nt >> 1][(nt & 1) * 2]);
                }
        }
    }

    int er = lane >> 2, ec = (lane & 3) << 1;
    #pragma unroll
    for (int mt = 0; mt < 4; mt++) {
        #pragma unroll
        for (int nt = 0; nt < 4; nt++) {
            int r0 = tile_m + warp_m + mt * 16 + er;
            int c0 = tile_n + warp_n + nt * 8 + ec;
            float t0 = g_t[r0], t1 = g_t[r0 + 8];
            *(float2*)&C[(size_t)r0 * N + c0] =
                make_float2(acc[mt][nt][0] + t0, acc[mt][nt][1] + t0);
            *(float2*)&C[(size_t)(r0 + 8) * N + c0] =
                make_float2(acc[mt][nt][2] + t1, acc[mt][nt][3] + t1);
        }
    }
}

// ---------------- feature-chunked CSR aggregation (fp16 Z) ----------------------
// mode 1: single fp16 -> outA; mode 2: fp16 hi/lo pair -> outHi/outLo (layer 3)
__global__ __launch_bounds__(256)
void agg_kernel(const __half* __restrict__ Z, const float* __restrict__ bias,
                __half* __restrict__ outA,
                __half* __restrict__ outHi, __half* __restrict__ outLo,
                int F, int mode) {
    int node = blockIdx.x * 8 + (threadIdx.x >> 5);
    int lane = threadIdx.x & 31;
    int chunk = blockIdx.y;
    int nvec = F >> 2;                  // 4-element groups per row
    int col = chunk * 32 + lane;        // group index

    float4 acc = make_float4(0.f, 0.f, 0.f, 0.f);
    int beg = g_rowptr[node], end = g_rowptr[node + 1];
    const uint2* Z2 = (const uint2*)Z;
    for (int e = beg; e < end; ++e) {
        int s = g_esrc[e];
        float w = g_ns[s];
        uint2 zu = Z2[(size_t)s * nvec + col];
        float2 z01 = __half22float2(*(__half2*)&zu.x);
        float2 z23 = __half22float2(*(__half2*)&zu.y);
        acc.x = fmaf(w, z01.x, acc.x);
        acc.y = fmaf(w, z01.y, acc.y);
        acc.z = fmaf(w, z23.x, acc.z);
        acc.w = fmaf(w, z23.y, acc.w);
    }
    float ndv = g_nd[node];
    float4 b = ((const float4*)bias)[col];
    float4 r;
    r.x = fmaxf(fmaf(ndv, acc.x, b.x), 0.f);
    r.y = fmaxf(fmaf(ndv, acc.y, b.y), 0.f);
    r.z = fmaxf(fmaf(ndv, acc.z, b.z), 0.f);
    r.w = fmaxf(fmaf(ndv, acc.w, b.w), 0.f);
    if (mode == 1) {
        uint2 u;
        u.x = pack_h2(r.x, r.y);
        u.y = pack_h2(r.z, r.w);
        ((uint2*)outA)[(size_t)node * nvec + col] = u;
    } else {
        __half hx = __float2half_rn(r.x), hy = __float2half_rn(r.y);
        __half hz = __float2half_rn(r.z), hw = __float2half_rn(r.w);
        uint2 h, l;
        h.x = pack_h2(__half2float(hx), __half2float(hy));
        h.y = pack_h2(__half2float(hz), __half2float(hw));
        l.x = pack_h2(r.x - __half2float(hx), r.y - __half2float(hy));
        l.y = pack_h2(r.z - __half2float(hz), r.w - __half2float(hw));
        ((uint2*)outHi)[(size_t)node * nvec + col] = h;
        ((uint2*)outLo)[(size_t)node * nvec + col] = l;
    }
}

// ---------------- launch --------------------------------------------------------
extern "C" void kernel_launch(void* const* d_in, const int* in_sizes, int n_in,
                              void* d_out, int out_size) {
    const float* x    = (const float*)d_in[0];
    const int*   src  = (const int*)d_in[1];
    const int*   dst  = (const int*)d_in[2];
    const int*   xidx = (const int*)d_in[3];
    const int*   cidx = (const int*)d_in[4];
    const float* W1   = (const float*)d_in[5];
    const float* b1   = (const float*)d_in[6];
    const float* W2   = (const float*)d_in[7];
    const float* b2   = (const float*)d_in[8];
    const float* W3   = (const float*)d_in[9];
    const float* b3   = (const float*)d_in[10];
    const float* Wp   = (const float*)d_in[11];
    const float* bp   = (const float*)d_in[12];
    const float* emb  = (const float*)d_in[13];
    float* out = (float*)d_out;

    static int smem_set = 0;
    if (!smem_set) {
        cudaFuncSetAttribute(gemm1_kernel<GK>,
                             cudaFuncAttributeMaxDynamicSharedMemorySize, G1_SMEM);
        cudaFuncSetAttribute(gemm2_kernel,
                             cudaFuncAttributeMaxDynamicSharedMemorySize, G2_SMEM);
        smem_set = 1;
    }

    __half *Zb, *A, *W1t, *W2t, *W3t, *Gf, *H3hi, *H3lo, *Ehi, *Elo;
    cudaGetSymbolAddress((void**)&Zb, g_Z);
    cudaGetSymbolAddress((void**)&A, g_A);
    cudaGetSymbolAddress((void**)&W1t, g_W1);
    cudaGetSymbolAddress((void**)&W2t, g_W2);
    cudaGetSymbolAddress((void**)&W3t, g_W3);
    cudaGetSymbolAddress((void**)&Gf, g_Gf);
    cudaGetSymbolAddress((void**)&H3hi, g_H3hi);
    cudaGetSymbolAddress((void**)&H3lo, g_H3lo);
    cudaGetSymbolAddress((void**)&Ehi, g_Ehi);
    cudaGetSymbolAddress((void**)&Elo, g_Elo);

    const int MB = (N_NODES + 127) / 128;   // 391

    // GEMM L1 at launch index 3 (ncu capture slot)
    conv_x_kernel<<<512, 256>>>(x);                                  // 0
    wprep_kernel<<<256, 256>>>(W1, W1t, GK, HID);                    // 1
    wprep_kernel<<<256, 256>>>(W2, W2t, GK, HID);                    // 2
    gemm1_kernel<GK><<<dim3(HID / 128, MB), 256, G1_SMEM>>>(         // 3  <- ncu
        A, W1t, Zb, N_NODES, HID);
    wprep_kernel<<<128, 256>>>(W3, W3t, GK, OUT_F);                  // 4
    gmat_kernel<<<N_C, 256>>>(emb, cidx, Wp, bp);                    // 5

    // graph preprocessing (needed before first agg)
    zero_deg_kernel<<<196, 256>>>();
    hist_kernel<<<512, 256>>>(src, dst);
    norm_kernel<<<196, 256>>>();
    scan1_kernel<<<SCAN_BLOCKS, 256>>>();
    scan2_kernel<<<1, 256>>>();
    scan3_kernel<<<SCAN_BLOCKS, 256>>>();
    fill_kernel<<<512, 256>>>(src, dst);

    // Layer 1 aggregation -> single fp16 activations
    agg_kernel<<<dim3(N_NODES / 8, HID / 128), 256>>>(Zb, b1, A, nullptr, nullptr, HID, 1);

    // Layer 2
    gemm1_kernel<GK><<<dim3(HID / 128, MB), 256, G1_SMEM>>>(A, W2t, Zb, N_NODES, HID);
    agg_kernel<<<dim3(N_NODES / 8, HID / 128), 256>>>(Zb, b2, A, nullptr, nullptr, HID, 1);

    // Layer 3 (N = 256): agg emits fp16 hi/lo pair (h3, 22-bit accurate)
    gemm1_kernel<GK><<<dim3(OUT_F / 128, MB), 256, G1_SMEM>>>(A, W3t, Zb, N_NODES, OUT_F);
    agg_kernel<<<dim3(N_NODES / 8, OUT_F / 128), 256>>>(Zb, b3, nullptr, H3hi, H3lo, OUT_F, 2);

    // dense pre-gather of selected encodings (hi/lo)
    enc_gather_kernel<<<(N_SEL * 32) / 256, 256>>>(xidx);

    // out = G @ E^T + t  — M=1024 (G single fp16), N=8192 (E hi/lo), K=256
    gemm2_kernel<<<dim3(N_SEL / 128, N_C / 128), 256, G2_SMEM>>>(
        Gf, Ehi, Elo, out, N_C, N_SEL);
}